// round 1
// baseline (speedup 1.0000x reference)
#include <cuda_runtime.h>
#include <math.h>
#include <stdint.h>

// Problem constants
#define BSZ 2
#define TT  2048
#define CC  1024
#define HH  16
#define LL  6
#define VV  32000
#define DD  64
#define FFD 4096
#define MT  (BSZ*TT)   // 4096 rows

// -------- scratch (device globals: allocation-free per harness rules) --------
__device__ float g_x [MT*CC];
__device__ float g_h [MT*CC];
__device__ float g_q [MT*CC];
__device__ float g_k [MT*CC];
__device__ float g_v [MT*CC];
__device__ float g_o [MT*CC];
__device__ float g_ff[(size_t)MT*FFD];

// ============================== embedding ==============================
__global__ void embed_kernel(const int* __restrict__ src,
                             const float* __restrict__ emb,
                             const float* __restrict__ pos,
                             float* __restrict__ out) {
    int row = blockIdx.x;              // 0..MT-1  (b*T + t)
    int tok = src[row];
    int t   = row & (TT - 1);
    const float4* e4 = (const float4*)(emb + (size_t)tok * CC);
    const float4* p4 = (const float4*)(pos + (size_t)t * CC);
    float4 e = e4[threadIdx.x];
    float4 p = p4[threadIdx.x];
    float4 r;
    r.x = e.x + p.x; r.y = e.y + p.y; r.z = e.z + p.z; r.w = e.w + p.w;
    ((float4*)(out + (size_t)row * CC))[threadIdx.x] = r;
}

// ============================== layernorm ==============================
__global__ void ln_kernel(const float* __restrict__ x,
                          const float* __restrict__ w,
                          const float* __restrict__ b,
                          float* __restrict__ out) {
    int row = blockIdx.x;
    int tid = threadIdx.x;
    __shared__ float red[8];
    __shared__ float sval;

    float4 v = ((const float4*)(x + (size_t)row * CC))[tid];

    // mean
    float s = v.x + v.y + v.z + v.w;
    #pragma unroll
    for (int o = 16; o; o >>= 1) s += __shfl_xor_sync(0xffffffffu, s, o);
    if ((tid & 31) == 0) red[tid >> 5] = s;
    __syncthreads();
    if (tid == 0) {
        float t = 0.f;
        #pragma unroll
        for (int i = 0; i < 8; i++) t += red[i];
        sval = t * (1.0f / CC);
    }
    __syncthreads();
    float mu = sval;

    // variance (two-pass, matches reference numerics)
    float dx = v.x - mu, dy = v.y - mu, dz = v.z - mu, dw = v.w - mu;
    float ss = dx*dx + dy*dy + dz*dz + dw*dw;
    #pragma unroll
    for (int o = 16; o; o >>= 1) ss += __shfl_xor_sync(0xffffffffu, ss, o);
    if ((tid & 31) == 0) red[tid >> 5] = ss;
    __syncthreads();
    if (tid == 0) {
        float t = 0.f;
        #pragma unroll
        for (int i = 0; i < 8; i++) t += red[i];
        sval = rsqrtf(t * (1.0f / CC) + 1e-5f);
    }
    __syncthreads();
    float inv = sval;

    float4 w4 = ((const float4*)w)[tid];
    float4 b4 = ((const float4*)b)[tid];
    float4 r;
    r.x = dx * inv * w4.x + b4.x;
    r.y = dy * inv * w4.y + b4.y;
    r.z = dz * inv * w4.z + b4.z;
    r.w = dw * inv * w4.w + b4.w;
    ((float4*)(out + (size_t)row * CC))[tid] = r;
}

// ============================== GEMM (fp32, 64x64x16) ==============================
// out[M,N] = A[M,K] @ W[K,N] (+bias) (gelu?) (+res)
// All M,N,K here are multiples of 64/16 -> no bounds checks.
#define BM 64
#define BN 64
#define BK 16

__global__ void __launch_bounds__(256)
gemm_kernel(const float* __restrict__ A, const float* __restrict__ W,
            const float* __restrict__ bias, const float* __restrict__ res,
            float* __restrict__ out, int M, int N, int K, int do_gelu) {
    __shared__ float As[BK][BM + 4];   // transposed A tile, pitch 68 (16B-aligned rows)
    __shared__ float Bs[BK][BN];

    int tid = threadIdx.x;
    int tx = tid & 15, ty = tid >> 4;
    int m0 = blockIdx.y * BM, n0 = blockIdx.x * BN;

    float acc[4][4];
    #pragma unroll
    for (int i = 0; i < 4; i++)
        #pragma unroll
        for (int j = 0; j < 4; j++) acc[i][j] = 0.f;

    for (int k0 = 0; k0 < K; k0 += BK) {
        #pragma unroll
        for (int i = 0; i < 4; i++) {
            int idx = tid + i * 256;
            int r  = idx >> 4, c  = idx & 15;
            As[c][r] = A[(size_t)(m0 + r) * K + k0 + c];
            int rb = idx >> 6, cb = idx & 63;
            Bs[rb][cb] = W[(size_t)(k0 + rb) * N + n0 + cb];
        }
        __syncthreads();
        #pragma unroll
        for (int kk = 0; kk < BK; kk++) {
            float4 a = *(const float4*)&As[kk][ty * 4];
            float4 b = *(const float4*)&Bs[kk][tx * 4];
            acc[0][0] += a.x*b.x; acc[0][1] += a.x*b.y; acc[0][2] += a.x*b.z; acc[0][3] += a.x*b.w;
            acc[1][0] += a.y*b.x; acc[1][1] += a.y*b.y; acc[1][2] += a.y*b.z; acc[1][3] += a.y*b.w;
            acc[2][0] += a.z*b.x; acc[2][1] += a.z*b.y; acc[2][2] += a.z*b.z; acc[2][3] += a.z*b.w;
            acc[3][0] += a.w*b.x; acc[3][1] += a.w*b.y; acc[3][2] += a.w*b.z; acc[3][3] += a.w*b.w;
        }
        __syncthreads();
    }

    #pragma unroll
    for (int i = 0; i < 4; i++) {
        int row = m0 + ty * 4 + i;
        #pragma unroll
        for (int j = 0; j < 4; j++) {
            int col = n0 + tx * 4 + j;
            float v = acc[i][j];
            if (bias) v += bias[col];
            if (do_gelu) v = 0.5f * v * (1.0f + erff(v * 0.70710678118654752f));
            if (res) v += res[(size_t)row * N + col];
            out[(size_t)row * N + col] = v;
        }
    }
}

// ============================== fused flash attention (fp32) ==============================
// grid: (T/64, H, B). One block processes 64 query rows for one (b,h).
// q/k/v/o are [B,T,C] with head h occupying columns [h*64, h*64+64).
#define ATTN_SMEM ((3 * 64 * 68 + 64 * 64) * 4)

__global__ void __launch_bounds__(256)
attn_kernel(const float* __restrict__ q, const float* __restrict__ k,
            const float* __restrict__ v, float* __restrict__ o) {
    extern __shared__ float sm[];
    float* Qt = sm;                 // [d][r] pitch 68 (q pre-scaled by 1/sqrt(D))
    float* Kt = sm + 64 * 68;       // [d][s] pitch 68
    float* Pt = sm + 2 * 64 * 68;   // [s][r] pitch 68
    float* Vs = sm + 3 * 64 * 68;   // [s][d] pitch 64

    int tid = threadIdx.x;
    int tx = tid & 15, ty = tid >> 4;
    int qt0 = blockIdx.x * 64;
    int h = blockIdx.y, b = blockIdx.z;
    size_t base = ((size_t)b * TT) * CC + (size_t)h * DD;

    // load Q tile (transposed, pre-scaled)
    #pragma unroll
    for (int i = 0; i < 16; i++) {
        int idx = tid + i * 256;
        int r = idx >> 6, d = idx & 63;
        Qt[d * 68 + r] = q[base + (size_t)(qt0 + r) * CC + d] * 0.125f;
    }

    float m[4], l[4], accO[4][4];
    #pragma unroll
    for (int i = 0; i < 4; i++) {
        m[i] = -1e30f; l[i] = 0.f;
        #pragma unroll
        for (int j = 0; j < 4; j++) accO[i][j] = 0.f;
    }

    for (int s0 = 0; s0 < TT; s0 += 64) {
        __syncthreads();   // prev PV done reading Vs/Pt; Qt ready on first iter
        #pragma unroll
        for (int i = 0; i < 16; i++) {
            int idx = tid + i * 256;
            int r = idx >> 6, d = idx & 63;
            Kt[d * 68 + r] = k[base + (size_t)(s0 + r) * CC + d];
            Vs[r * 64 + d] = v[base + (size_t)(s0 + r) * CC + d];
        }
        __syncthreads();

        // S = (Q/8) K^T
        float s[4][4];
        #pragma unroll
        for (int i = 0; i < 4; i++)
            #pragma unroll
            for (int j = 0; j < 4; j++) s[i][j] = 0.f;
        #pragma unroll 8
        for (int d = 0; d < 64; d++) {
            float4 a  = *(const float4*)&Qt[d * 68 + ty * 4];
            float4 bb = *(const float4*)&Kt[d * 68 + tx * 4];
            s[0][0] += a.x*bb.x; s[0][1] += a.x*bb.y; s[0][2] += a.x*bb.z; s[0][3] += a.x*bb.w;
            s[1][0] += a.y*bb.x; s[1][1] += a.y*bb.y; s[1][2] += a.y*bb.z; s[1][3] += a.y*bb.w;
            s[2][0] += a.z*bb.x; s[2][1] += a.z*bb.y; s[2][2] += a.z*bb.z; s[2][3] += a.z*bb.w;
            s[3][0] += a.w*bb.x; s[3][1] += a.w*bb.y; s[3][2] += a.w*bb.z; s[3][3] += a.w*bb.w;
        }

        // online softmax (row stats shared across the 16 tx lanes of each ty)
        #pragma unroll
        for (int i = 0; i < 4; i++) {
            float rm = fmaxf(fmaxf(s[i][0], s[i][1]), fmaxf(s[i][2], s[i][3]));
            rm = fmaxf(rm, __shfl_xor_sync(0xffffffffu, rm, 1));
            rm = fmaxf(rm, __shfl_xor_sync(0xffffffffu, rm, 2));
            rm = fmaxf(rm, __shfl_xor_sync(0xffffffffu, rm, 4));
            rm = fmaxf(rm, __shfl_xor_sync(0xffffffffu, rm, 8));
            float mn = fmaxf(m[i], rm);
            float corr = expf(m[i] - mn);
            m[i] = mn;
            float rs = 0.f;
            #pragma unroll
            for (int j = 0; j < 4; j++) {
                float p = expf(s[i][j] - mn);
                s[i][j] = p;
                rs += p;
            }
            rs += __shfl_xor_sync(0xffffffffu, rs, 1);
            rs += __shfl_xor_sync(0xffffffffu, rs, 2);
            rs += __shfl_xor_sync(0xffffffffu, rs, 4);
            rs += __shfl_xor_sync(0xffffffffu, rs, 8);
            l[i] = l[i] * corr + rs;
            #pragma unroll
            for (int j = 0; j < 4; j++) accO[i][j] *= corr;
        }

        // stage P (transposed) for the PV GEMM
        #pragma unroll
        for (int i = 0; i < 4; i++)
            #pragma unroll
            for (int j = 0; j < 4; j++)
                Pt[(tx * 4 + j) * 68 + ty * 4 + i] = s[i][j];
        __syncthreads();

        // accO += P @ V
        #pragma unroll 8
        for (int j = 0; j < 64; j++) {
            float4 p  = *(const float4*)&Pt[j * 68 + ty * 4];
            float4 vv = *(const float4*)&Vs[j * 64 + tx * 4];
            accO[0][0] += p.x*vv.x; accO[0][1] += p.x*vv.y; accO[0][2] += p.x*vv.z; accO[0][3] += p.x*vv.w;
            accO[1][0] += p.y*vv.x; accO[1][1] += p.y*vv.y; accO[1][2] += p.y*vv.z; accO[1][3] += p.y*vv.w;
            accO[2][0] += p.z*vv.x; accO[2][1] += p.z*vv.y; accO[2][2] += p.z*vv.z; accO[2][3] += p.z*vv.w;
            accO[3][0] += p.w*vv.x; accO[3][1] += p.w*vv.y; accO[3][2] += p.w*vv.z; accO[3][3] += p.w*vv.w;
        }
    }

    #pragma unroll
    for (int i = 0; i < 4; i++) {
        float invl = 1.0f / l[i];
        int t = qt0 + ty * 4 + i;
        #pragma unroll
        for (int j = 0; j < 4; j++)
            o[base + (size_t)t * CC + tx * 4 + j] = accO[i][j] * invl;
    }
}

// ============================== launcher ==============================
extern "C" void kernel_launch(void* const* d_in, const int* in_sizes, int n_in,
                              void* d_out, int out_size) {
    (void)in_sizes; (void)n_in; (void)out_size;

    const int*   src     = (const int*)  d_in[0];
    const float* src_emb = (const float*)d_in[1];
    const float* pos_emb = (const float*)d_in[2];
    const float* ln1_w   = (const float*)d_in[3];
    const float* ln1_b   = (const float*)d_in[4];
    const float* wq      = (const float*)d_in[5];
    const float* bq      = (const float*)d_in[6];
    const float* wk      = (const float*)d_in[7];
    const float* bk      = (const float*)d_in[8];
    const float* wv      = (const float*)d_in[9];
    const float* bv      = (const float*)d_in[10];
    const float* wo      = (const float*)d_in[11];
    const float* bo      = (const float*)d_in[12];
    const float* ln2_w   = (const float*)d_in[13];
    const float* ln2_b   = (const float*)d_in[14];
    const float* w1      = (const float*)d_in[15];
    const float* b1      = (const float*)d_in[16];
    const float* w2      = (const float*)d_in[17];
    const float* b2      = (const float*)d_in[18];
    const float* lnf_w   = (const float*)d_in[19];
    const float* lnf_b   = (const float*)d_in[20];
    const float* head_w  = (const float*)d_in[21];

    float *xb, *hb, *qb, *kb, *vb, *ob, *fb;
    cudaGetSymbolAddress((void**)&xb, g_x);
    cudaGetSymbolAddress((void**)&hb, g_h);
    cudaGetSymbolAddress((void**)&qb, g_q);
    cudaGetSymbolAddress((void**)&kb, g_k);
    cudaGetSymbolAddress((void**)&vb, g_v);
    cudaGetSymbolAddress((void**)&ob, g_o);
    cudaGetSymbolAddress((void**)&fb, g_ff);

    cudaFuncSetAttribute(attn_kernel, cudaFuncAttributeMaxDynamicSharedMemorySize, ATTN_SMEM);

    embed_kernel<<<MT, 256>>>(src, src_emb, pos_emb, xb);

    dim3 gC(CC / BN, MT / BM);     // N=1024
    dim3 gF(FFD / BN, MT / BM);    // N=4096
    dim3 gA(TT / 64, HH, BSZ);

    for (int l = 0; l < LL; l++) {
        size_t wOff  = (size_t)l * CC * CC;
        size_t w1Off = (size_t)l * CC * FFD;
        size_t w2Off = (size_t)l * FFD * CC;

        ln_kernel<<<MT, 256>>>(xb, ln1_w + l * CC, ln1_b + l * CC, hb);
        gemm_kernel<<<gC, 256>>>(hb, wq + wOff, bq + l * CC, nullptr, qb, MT, CC, CC, 0);
        gemm_kernel<<<gC, 256>>>(hb, wk + wOff, bk + l * CC, nullptr, kb, MT, CC, CC, 0);
        gemm_kernel<<<gC, 256>>>(hb, wv + wOff, bv + l * CC, nullptr, vb, MT, CC, CC, 0);

        attn_kernel<<<gA, 256, ATTN_SMEM>>>(qb, kb, vb, ob);

        gemm_kernel<<<gC, 256>>>(ob, wo + wOff, bo + l * CC, xb, xb, MT, CC, CC, 0);

        ln_kernel<<<MT, 256>>>(xb, ln2_w + l * CC, ln2_b + l * CC, hb);
        gemm_kernel<<<gF, 256>>>(hb, w1 + w1Off, b1 + l * FFD, nullptr, fb, MT, FFD, CC, 1);
        gemm_kernel<<<gC, 256>>>(fb, w2 + w2Off, b2 + l * CC, xb, xb, MT, CC, FFD, 0);
    }

    ln_kernel<<<MT, 256>>>(xb, lnf_w, lnf_b, hb);
    dim3 gH(VV / BN, MT / BM);
    gemm_kernel<<<gH, 256>>>(hb, head_w, nullptr, nullptr, (float*)d_out, MT, VV, CC, 0);
}

// round 3
// speedup vs baseline: 2.1707x; 2.1707x over previous
#include <cuda_runtime.h>
#include <math.h>
#include <stdint.h>

// Problem constants
#define BSZ 2
#define TT  2048
#define CC  1024
#define HH  16
#define LL  6
#define VV  32000
#define DD  64
#define FFD 4096
#define MT  (BSZ*TT)   // 4096 rows

// -------- scratch (device globals: allocation-free per harness rules) --------
__device__ float g_x [MT*CC];
__device__ float g_h [MT*CC];
__device__ float g_q [MT*CC];
__device__ float g_k [MT*CC];
__device__ float g_v [MT*CC];
__device__ float g_o [MT*CC];
__device__ float g_ff[(size_t)MT*FFD];

// ============================== helpers ==============================
__device__ __forceinline__ uint32_t f2tf32(float x) {
    uint32_t r; asm("cvt.rna.tf32.f32 %0, %1;" : "=r"(r) : "f"(x)); return r;
}

// m16n8k8 tf32 mma (row.col), fp32 accumulate — sm_80+ instruction, no 'a' feature.
__device__ __forceinline__ void mma_tf32(float* d, const uint32_t* a, const uint32_t* b,
                                         const float* c) {
    asm volatile(
        "mma.sync.aligned.m16n8k8.row.col.f32.tf32.tf32.f32 "
        "{%0,%1,%2,%3}, {%4,%5,%6,%7}, {%8,%9}, {%10,%11,%12,%13};"
        : "=f"(d[0]), "=f"(d[1]), "=f"(d[2]), "=f"(d[3])
        : "r"(a[0]), "r"(a[1]), "r"(a[2]), "r"(a[3]),
          "r"(b[0]), "r"(b[1]),
          "f"(c[0]), "f"(c[1]), "f"(c[2]), "f"(c[3]));
}

// ============================== embedding ==============================
__global__ void embed_kernel(const int* __restrict__ src,
                             const float* __restrict__ emb,
                             const float* __restrict__ pos,
                             float* __restrict__ out) {
    int row = blockIdx.x;
    int tok = src[row];
    int t   = row & (TT - 1);
    float4 e = ((const float4*)(emb + (size_t)tok * CC))[threadIdx.x];
    float4 p = ((const float4*)(pos + (size_t)t * CC))[threadIdx.x];
    float4 r;
    r.x = e.x + p.x; r.y = e.y + p.y; r.z = e.z + p.z; r.w = e.w + p.w;
    ((float4*)(out + (size_t)row * CC))[threadIdx.x] = r;
}

// ============================== layernorm ==============================
__global__ void ln_kernel(const float* __restrict__ x,
                          const float* __restrict__ w,
                          const float* __restrict__ b,
                          float* __restrict__ out) {
    int row = blockIdx.x;
    int tid = threadIdx.x;
    __shared__ float red[8];
    __shared__ float sval;

    float4 v = ((const float4*)(x + (size_t)row * CC))[tid];
    float s = v.x + v.y + v.z + v.w;
    #pragma unroll
    for (int o = 16; o; o >>= 1) s += __shfl_xor_sync(0xffffffffu, s, o);
    if ((tid & 31) == 0) red[tid >> 5] = s;
    __syncthreads();
    if (tid == 0) {
        float t = 0.f;
        #pragma unroll
        for (int i = 0; i < 8; i++) t += red[i];
        sval = t * (1.0f / CC);
    }
    __syncthreads();
    float mu = sval;
    float dx = v.x - mu, dy = v.y - mu, dz = v.z - mu, dw = v.w - mu;
    float ss = dx*dx + dy*dy + dz*dz + dw*dw;
    #pragma unroll
    for (int o = 16; o; o >>= 1) ss += __shfl_xor_sync(0xffffffffu, ss, o);
    if ((tid & 31) == 0) red[tid >> 5] = ss;
    __syncthreads();
    if (tid == 0) {
        float t = 0.f;
        #pragma unroll
        for (int i = 0; i < 8; i++) t += red[i];
        sval = rsqrtf(t * (1.0f / CC) + 1e-5f);
    }
    __syncthreads();
    float inv = sval;
    float4 w4 = ((const float4*)w)[tid];
    float4 b4 = ((const float4*)b)[tid];
    float4 r;
    r.x = dx * inv * w4.x + b4.x;
    r.y = dy * inv * w4.y + b4.y;
    r.z = dz * inv * w4.z + b4.z;
    r.w = dw * inv * w4.w + b4.w;
    ((float4*)(out + (size_t)row * CC))[tid] = r;
}

// ============================== tf32 tensor-core GEMM ==============================
// out[M,N] = A[M,K] @ W[K,N] (+bias) (gelu?) (+res)
// CTA: 128x128x16, 8 warps in 2(m) x 4(n), each warp 64x32 = 4x4 m16n8k8 tiles.
#define GBM 128
#define GBN 128
#define GBK 16
#define APITCH 20     // As[m][k] pitch -> conflict-free frag loads
#define BPITCH 136    // Bs[k][n] pitch -> conflict-free frag loads

__global__ void __launch_bounds__(256, 2)
mma_gemm(const float* __restrict__ A, const float* __restrict__ W,
         const float* __restrict__ bias, const float* __restrict__ res,
         float* __restrict__ out, int M, int N, int K, int do_gelu) {
    __shared__ uint32_t As[GBM * APITCH];   // [m][k]
    __shared__ uint32_t Bs[GBK * BPITCH];   // [k][n]

    int tid  = threadIdx.x;
    int lane = tid & 31;
    int wid  = tid >> 5;
    int wm   = (wid >> 2) * 64;     // warp m offset (0 or 64)
    int wn   = (wid & 3) * 32;      // warp n offset (0,32,64,96)
    int m0 = blockIdx.y * GBM, n0 = blockIdx.x * GBN;

    int lq = lane >> 2;             // lane/4 : 0..7
    int lr = lane & 3;              // lane%4 : 0..3

    float acc[4][4][4];
    #pragma unroll
    for (int i = 0; i < 4; i++)
        #pragma unroll
        for (int j = 0; j < 4; j++)
            #pragma unroll
            for (int r = 0; r < 4; r++) acc[i][j][r] = 0.f;

    for (int k0 = 0; k0 < K; k0 += GBK) {
        // ---- stage A tile: As[m][k], coalesced float4 global reads ----
        #pragma unroll
        for (int i = 0; i < 2; i++) {
            int idx = tid + i * 256;           // 0..511
            int m = idx >> 2, c4 = idx & 3;
            float4 v = *(const float4*)(A + (size_t)(m0 + m) * K + k0 + c4 * 4);
            uint32_t* p = &As[m * APITCH + c4 * 4];
            p[0] = f2tf32(v.x); p[1] = f2tf32(v.y); p[2] = f2tf32(v.z); p[3] = f2tf32(v.w);
        }
        // ---- stage B tile: Bs[k][n], coalesced float4 global reads ----
        #pragma unroll
        for (int i = 0; i < 2; i++) {
            int idx = tid + i * 256;           // 0..511
            int k = idx >> 5, n4 = idx & 31;
            float4 v = *(const float4*)(W + (size_t)(k0 + k) * N + n0 + n4 * 4);
            uint32_t* p = &Bs[k * BPITCH + n4 * 4];
            p[0] = f2tf32(v.x); p[1] = f2tf32(v.y); p[2] = f2tf32(v.z); p[3] = f2tf32(v.w);
        }
        __syncthreads();

        #pragma unroll
        for (int ks = 0; ks < 2; ks++) {
            int k8 = ks * 8;
            uint32_t a[4][4], b[4][2];
            #pragma unroll
            for (int mt = 0; mt < 4; mt++) {
                int r = wm + mt * 16 + lq;
                a[mt][0] = As[r * APITCH + k8 + lr];
                a[mt][1] = As[(r + 8) * APITCH + k8 + lr];
                a[mt][2] = As[r * APITCH + k8 + lr + 4];
                a[mt][3] = As[(r + 8) * APITCH + k8 + lr + 4];
            }
            #pragma unroll
            for (int nt = 0; nt < 4; nt++) {
                int c = wn + nt * 8 + lq;
                b[nt][0] = Bs[(k8 + lr) * BPITCH + c];
                b[nt][1] = Bs[(k8 + 4 + lr) * BPITCH + c];
            }
            #pragma unroll
            for (int mt = 0; mt < 4; mt++)
                #pragma unroll
                for (int nt = 0; nt < 4; nt++)
                    mma_tf32(acc[mt][nt], a[mt], b[nt], acc[mt][nt]);
        }
        __syncthreads();
    }

    // ---- epilogue ----
    #pragma unroll
    for (int mt = 0; mt < 4; mt++) {
        int row0 = m0 + wm + mt * 16 + lq;
        #pragma unroll
        for (int nt = 0; nt < 4; nt++) {
            int col = n0 + wn + nt * 8 + lr * 2;
            #pragma unroll
            for (int half = 0; half < 2; half++) {
                int row = row0 + half * 8;
                float v0 = acc[mt][nt][half * 2 + 0];
                float v1 = acc[mt][nt][half * 2 + 1];
                if (bias) {
                    v0 += __ldg(bias + col);
                    v1 += __ldg(bias + col + 1);
                }
                if (do_gelu) {
                    v0 = 0.5f * v0 * (1.0f + erff(v0 * 0.70710678118654752f));
                    v1 = 0.5f * v1 * (1.0f + erff(v1 * 0.70710678118654752f));
                }
                if (res) {
                    const float2 rr = *(const float2*)(res + (size_t)row * N + col);
                    v0 += rr.x; v1 += rr.y;
                }
                float2 o2; o2.x = v0; o2.y = v1;
                *(float2*)(out + (size_t)row * N + col) = o2;
            }
        }
    }
}

// ============================== fused flash attention (fp32) ==============================
#define ATTN_SMEM ((3 * 64 * 68 + 64 * 64) * 4)

__global__ void __launch_bounds__(256)
attn_kernel(const float* __restrict__ q, const float* __restrict__ k,
            const float* __restrict__ v, float* __restrict__ o) {
    extern __shared__ float sm[];
    float* Qt = sm;
    float* Kt = sm + 64 * 68;
    float* Pt = sm + 2 * 64 * 68;
    float* Vs = sm + 3 * 64 * 68;

    int tid = threadIdx.x;
    int tx = tid & 15, ty = tid >> 4;
    int qt0 = blockIdx.x * 64;
    int h = blockIdx.y, b = blockIdx.z;
    size_t base = ((size_t)b * TT) * CC + (size_t)h * DD;

    #pragma unroll
    for (int i = 0; i < 16; i++) {
        int idx = tid + i * 256;
        int r = idx >> 6, d = idx & 63;
        Qt[d * 68 + r] = q[base + (size_t)(qt0 + r) * CC + d] * 0.125f;
    }

    float m[4], l[4], accO[4][4];
    #pragma unroll
    for (int i = 0; i < 4; i++) {
        m[i] = -1e30f; l[i] = 0.f;
        #pragma unroll
        for (int j = 0; j < 4; j++) accO[i][j] = 0.f;
    }

    for (int s0 = 0; s0 < TT; s0 += 64) {
        __syncthreads();
        #pragma unroll
        for (int i = 0; i < 16; i++) {
            int idx = tid + i * 256;
            int r = idx >> 6, d = idx & 63;
            Kt[d * 68 + r] = k[base + (size_t)(s0 + r) * CC + d];
            Vs[r * 64 + d] = v[base + (size_t)(s0 + r) * CC + d];
        }
        __syncthreads();

        float s[4][4];
        #pragma unroll
        for (int i = 0; i < 4; i++)
            #pragma unroll
            for (int j = 0; j < 4; j++) s[i][j] = 0.f;
        #pragma unroll 8
        for (int d = 0; d < 64; d++) {
            float4 a  = *(const float4*)&Qt[d * 68 + ty * 4];
            float4 bb = *(const float4*)&Kt[d * 68 + tx * 4];
            s[0][0] += a.x*bb.x; s[0][1] += a.x*bb.y; s[0][2] += a.x*bb.z; s[0][3] += a.x*bb.w;
            s[1][0] += a.y*bb.x; s[1][1] += a.y*bb.y; s[1][2] += a.y*bb.z; s[1][3] += a.y*bb.w;
            s[2][0] += a.z*bb.x; s[2][1] += a.z*bb.y; s[2][2] += a.z*bb.z; s[2][3] += a.z*bb.w;
            s[3][0] += a.w*bb.x; s[3][1] += a.w*bb.y; s[3][2] += a.w*bb.z; s[3][3] += a.w*bb.w;
        }

        #pragma unroll
        for (int i = 0; i < 4; i++) {
            float rm = fmaxf(fmaxf(s[i][0], s[i][1]), fmaxf(s[i][2], s[i][3]));
            rm = fmaxf(rm, __shfl_xor_sync(0xffffffffu, rm, 1));
            rm = fmaxf(rm, __shfl_xor_sync(0xffffffffu, rm, 2));
            rm = fmaxf(rm, __shfl_xor_sync(0xffffffffu, rm, 4));
            rm = fmaxf(rm, __shfl_xor_sync(0xffffffffu, rm, 8));
            float mn = fmaxf(m[i], rm);
            float corr = expf(m[i] - mn);
            m[i] = mn;
            float rs = 0.f;
            #pragma unroll
            for (int j = 0; j < 4; j++) {
                float p = expf(s[i][j] - mn);
                s[i][j] = p;
                rs += p;
            }
            rs += __shfl_xor_sync(0xffffffffu, rs, 1);
            rs += __shfl_xor_sync(0xffffffffu, rs, 2);
            rs += __shfl_xor_sync(0xffffffffu, rs, 4);
            rs += __shfl_xor_sync(0xffffffffu, rs, 8);
            l[i] = l[i] * corr + rs;
            #pragma unroll
            for (int j = 0; j < 4; j++) accO[i][j] *= corr;
        }

        #pragma unroll
        for (int i = 0; i < 4; i++)
            #pragma unroll
            for (int j = 0; j < 4; j++)
                Pt[(tx * 4 + j) * 68 + ty * 4 + i] = s[i][j];
        __syncthreads();

        #pragma unroll 8
        for (int j = 0; j < 64; j++) {
            float4 p  = *(const float4*)&Pt[j * 68 + ty * 4];
            float4 vv = *(const float4*)&Vs[j * 64 + tx * 4];
            accO[0][0] += p.x*vv.x; accO[0][1] += p.x*vv.y; accO[0][2] += p.x*vv.z; accO[0][3] += p.x*vv.w;
            accO[1][0] += p.y*vv.x; accO[1][1] += p.y*vv.y; accO[1][2] += p.y*vv.z; accO[1][3] += p.y*vv.w;
            accO[2][0] += p.z*vv.x; accO[2][1] += p.z*vv.y; accO[2][2] += p.z*vv.z; accO[2][3] += p.z*vv.w;
            accO[3][0] += p.w*vv.x; accO[3][1] += p.w*vv.y; accO[3][2] += p.w*vv.z; accO[3][3] += p.w*vv.w;
        }
    }

    #pragma unroll
    for (int i = 0; i < 4; i++) {
        float invl = 1.0f / l[i];
        int t = qt0 + ty * 4 + i;
        #pragma unroll
        for (int j = 0; j < 4; j++)
            o[base + (size_t)t * CC + tx * 4 + j] = accO[i][j] * invl;
    }
}

// ============================== launcher ==============================
extern "C" void kernel_launch(void* const* d_in, const int* in_sizes, int n_in,
                              void* d_out, int out_size) {
    (void)in_sizes; (void)n_in; (void)out_size;

    const int*   src     = (const int*)  d_in[0];
    const float* src_emb = (const float*)d_in[1];
    const float* pos_emb = (const float*)d_in[2];
    const float* ln1_w   = (const float*)d_in[3];
    const float* ln1_b   = (const float*)d_in[4];
    const float* wq      = (const float*)d_in[5];
    const float* bq      = (const float*)d_in[6];
    const float* wk      = (const float*)d_in[7];
    const float* bk      = (const float*)d_in[8];
    const float* wv      = (const float*)d_in[9];
    const float* bv      = (const float*)d_in[10];
    const float* wo      = (const float*)d_in[11];
    const float* bo      = (const float*)d_in[12];
    const float* ln2_w   = (const float*)d_in[13];
    const float* ln2_b   = (const float*)d_in[14];
    const float* w1      = (const float*)d_in[15];
    const float* b1      = (const float*)d_in[16];
    const float* w2      = (const float*)d_in[17];
    const float* b2      = (const float*)d_in[18];
    const float* lnf_w   = (const float*)d_in[19];
    const float* lnf_b   = (const float*)d_in[20];
    const float* head_w  = (const float*)d_in[21];

    float *xb, *hb, *qb, *kb, *vb, *ob, *fb;
    cudaGetSymbolAddress((void**)&xb, g_x);
    cudaGetSymbolAddress((void**)&hb, g_h);
    cudaGetSymbolAddress((void**)&qb, g_q);
    cudaGetSymbolAddress((void**)&kb, g_k);
    cudaGetSymbolAddress((void**)&vb, g_v);
    cudaGetSymbolAddress((void**)&ob, g_o);
    cudaGetSymbolAddress((void**)&fb, g_ff);

    cudaFuncSetAttribute(attn_kernel, cudaFuncAttributeMaxDynamicSharedMemorySize, ATTN_SMEM);

    embed_kernel<<<MT, 256>>>(src, src_emb, pos_emb, xb);

    dim3 gC(CC / GBN, MT / GBM);    // (8, 32)
    dim3 gF(FFD / GBN, MT / GBM);   // (32, 32)
    dim3 gH(VV / GBN, MT / GBM);    // (250, 32)
    dim3 gA(TT / 64, HH, BSZ);

    for (int l = 0; l < LL; l++) {
        size_t wOff  = (size_t)l * CC * CC;
        size_t w1Off = (size_t)l * CC * FFD;
        size_t w2Off = (size_t)l * FFD * CC;

        ln_kernel<<<MT, 256>>>(xb, ln1_w + l * CC, ln1_b + l * CC, hb);
        mma_gemm<<<gC, 256>>>(hb, wq + wOff, bq + l * CC, nullptr, qb, MT, CC, CC, 0);
        mma_gemm<<<gC, 256>>>(hb, wk + wOff, bk + l * CC, nullptr, kb, MT, CC, CC, 0);
        mma_gemm<<<gC, 256>>>(hb, wv + wOff, bv + l * CC, nullptr, vb, MT, CC, CC, 0);

        attn_kernel<<<gA, 256, ATTN_SMEM>>>(qb, kb, vb, ob);

        mma_gemm<<<gC, 256>>>(ob, wo + wOff, bo + l * CC, xb, xb, MT, CC, CC, 0);

        ln_kernel<<<MT, 256>>>(xb, ln2_w + l * CC, ln2_b + l * CC, hb);
        mma_gemm<<<gF, 256>>>(hb, w1 + w1Off, b1 + l * FFD, nullptr, fb, MT, FFD, CC, 1);
        mma_gemm<<<gC, 256>>>(fb, w2 + w2Off, b2 + l * CC, xb, xb, MT, CC, FFD, 0);
    }

    ln_kernel<<<MT, 256>>>(xb, lnf_w, lnf_b, hb);
    mma_gemm<<<gH, 256>>>(hb, head_w, nullptr, nullptr, (float*)d_out, MT, VV, CC, 0);
}

// round 4
// speedup vs baseline: 2.2304x; 1.0275x over previous
#include <cuda_runtime.h>
#include <math.h>
#include <stdint.h>

// Problem constants
#define BSZ 2
#define TT  2048
#define CC  1024
#define HH  16
#define LL  6
#define VV  32000
#define DD  64
#define FFD 4096
#define MT  (BSZ*TT)   // 4096 rows

// -------- scratch (device globals: allocation-free per harness rules) --------
__device__ float g_x [MT*CC];
__device__ float g_h [MT*CC];
__device__ float g_q [MT*CC];
__device__ float g_k [MT*CC];
__device__ float g_v [MT*CC];
__device__ float g_o [MT*CC];
__device__ float g_ff[(size_t)MT*FFD];

// ============================== helpers ==============================
__device__ __forceinline__ uint32_t f2tf32(float x) {
    uint32_t r; asm("cvt.rna.tf32.f32 %0, %1;" : "=r"(r) : "f"(x)); return r;
}

// m16n8k8 tf32 mma (row.col), fp32 accumulate — sm_80+ instruction, no 'a' feature.
__device__ __forceinline__ void mma_tf32(float* d, const uint32_t* a, const uint32_t* b,
                                         const float* c) {
    asm volatile(
        "mma.sync.aligned.m16n8k8.row.col.f32.tf32.tf32.f32 "
        "{%0,%1,%2,%3}, {%4,%5,%6,%7}, {%8,%9}, {%10,%11,%12,%13};"
        : "=f"(d[0]), "=f"(d[1]), "=f"(d[2]), "=f"(d[3])
        : "r"(a[0]), "r"(a[1]), "r"(a[2]), "r"(a[3]),
          "r"(b[0]), "r"(b[1]),
          "f"(c[0]), "f"(c[1]), "f"(c[2]), "f"(c[3]));
}

// ============================== embedding ==============================
__global__ void embed_kernel(const int* __restrict__ src,
                             const float* __restrict__ emb,
                             const float* __restrict__ pos,
                             float* __restrict__ out) {
    int row = blockIdx.x;
    int tok = src[row];
    int t   = row & (TT - 1);
    float4 e = ((const float4*)(emb + (size_t)tok * CC))[threadIdx.x];
    float4 p = ((const float4*)(pos + (size_t)t * CC))[threadIdx.x];
    float4 r;
    r.x = e.x + p.x; r.y = e.y + p.y; r.z = e.z + p.z; r.w = e.w + p.w;
    ((float4*)(out + (size_t)row * CC))[threadIdx.x] = r;
}

// ============================== layernorm ==============================
__global__ void ln_kernel(const float* __restrict__ x,
                          const float* __restrict__ w,
                          const float* __restrict__ b,
                          float* __restrict__ out) {
    int row = blockIdx.x;
    int tid = threadIdx.x;
    __shared__ float red[8];
    __shared__ float sval;

    float4 v = ((const float4*)(x + (size_t)row * CC))[tid];
    float s = v.x + v.y + v.z + v.w;
    #pragma unroll
    for (int o = 16; o; o >>= 1) s += __shfl_xor_sync(0xffffffffu, s, o);
    if ((tid & 31) == 0) red[tid >> 5] = s;
    __syncthreads();
    if (tid == 0) {
        float t = 0.f;
        #pragma unroll
        for (int i = 0; i < 8; i++) t += red[i];
        sval = t * (1.0f / CC);
    }
    __syncthreads();
    float mu = sval;
    float dx = v.x - mu, dy = v.y - mu, dz = v.z - mu, dw = v.w - mu;
    float ss = dx*dx + dy*dy + dz*dz + dw*dw;
    #pragma unroll
    for (int o = 16; o; o >>= 1) ss += __shfl_xor_sync(0xffffffffu, ss, o);
    if ((tid & 31) == 0) red[tid >> 5] = ss;
    __syncthreads();
    if (tid == 0) {
        float t = 0.f;
        #pragma unroll
        for (int i = 0; i < 8; i++) t += red[i];
        sval = rsqrtf(t * (1.0f / CC) + 1e-5f);
    }
    __syncthreads();
    float inv = sval;
    float4 w4 = ((const float4*)w)[tid];
    float4 b4 = ((const float4*)b)[tid];
    float4 r;
    r.x = dx * inv * w4.x + b4.x;
    r.y = dy * inv * w4.y + b4.y;
    r.z = dz * inv * w4.z + b4.z;
    r.w = dw * inv * w4.w + b4.w;
    ((float4*)(out + (size_t)row * CC))[tid] = r;
}

// ============================== tf32 tensor-core GEMM (pipelined) ==============================
// out[M,N] = A[M,K] @ W[K,N] (+bias) (gelu?) (+res)
// CTA: 128x128x16, 8 warps in 2(m) x 4(n), each warp 64x32 = 4x4 m16n8k8 tiles.
// Double-buffered SMEM + register prefetch: LDG(c+1) issued before MMA(c),
// STS(c+1) after, single __syncthreads per chunk.
#define GBM 128
#define GBN 128
#define GBK 16
#define APITCH 20     // As[m][k] pitch -> conflict-free frag loads
#define BPITCH 136    // Bs[k][n] pitch -> conflict-free frag loads

__global__ void __launch_bounds__(256, 2)
mma_gemm(const float* __restrict__ A, const float* __restrict__ W,
         const float* __restrict__ bias, const float* __restrict__ res,
         float* __restrict__ out, int M, int N, int K, int do_gelu) {
    __shared__ uint32_t As[2][GBM * APITCH];   // [m][k]
    __shared__ uint32_t Bs[2][GBK * BPITCH];   // [k][n]

    int tid  = threadIdx.x;
    int lane = tid & 31;
    int wid  = tid >> 5;
    int wm   = (wid >> 2) * 64;     // warp m offset (0 or 64)
    int wn   = (wid & 3) * 32;      // warp n offset (0,32,64,96)
    int m0 = blockIdx.y * GBM, n0 = blockIdx.x * GBN;

    int lq = lane >> 2;             // lane/4 : 0..7
    int lr = lane & 3;              // lane%4 : 0..3

    // per-thread staging coordinates (2 A vecs + 2 B vecs per chunk)
    int am0 = tid >> 2,          ac0 = (tid & 3) * 4;          // A idx = tid
    int am1 = (tid + 256) >> 2,  ac1 = (tid & 3) * 4;          // A idx = tid+256
    int bk0 = tid >> 5,          bn0 = (tid & 31) * 4;         // B idx = tid
    int bk1 = (tid + 256) >> 5,  bn1 = (tid & 31) * 4;         // B idx = tid+256

    const float* Arow0 = A + (size_t)(m0 + am0) * K + ac0;
    const float* Arow1 = A + (size_t)(m0 + am1) * K + ac1;
    const float* Wrow0 = W + (size_t)bk0 * N + n0 + bn0;
    const float* Wrow1 = W + (size_t)bk1 * N + n0 + bn1;

    float acc[4][4][4];
    #pragma unroll
    for (int i = 0; i < 4; i++)
        #pragma unroll
        for (int j = 0; j < 4; j++)
            #pragma unroll
            for (int r = 0; r < 4; r++) acc[i][j][r] = 0.f;

    float4 ra0, ra1, rb0, rb1;

    // ---- prologue: load + stage chunk 0 ----
    ra0 = *(const float4*)(Arow0);
    ra1 = *(const float4*)(Arow1);
    rb0 = *(const float4*)(Wrow0);
    rb1 = *(const float4*)(Wrow1);
    {
        uint32_t* p;
        p = &As[0][am0 * APITCH + ac0];
        p[0]=f2tf32(ra0.x); p[1]=f2tf32(ra0.y); p[2]=f2tf32(ra0.z); p[3]=f2tf32(ra0.w);
        p = &As[0][am1 * APITCH + ac1];
        p[0]=f2tf32(ra1.x); p[1]=f2tf32(ra1.y); p[2]=f2tf32(ra1.z); p[3]=f2tf32(ra1.w);
        p = &Bs[0][bk0 * BPITCH + bn0];
        p[0]=f2tf32(rb0.x); p[1]=f2tf32(rb0.y); p[2]=f2tf32(rb0.z); p[3]=f2tf32(rb0.w);
        p = &Bs[0][bk1 * BPITCH + bn1];
        p[0]=f2tf32(rb1.x); p[1]=f2tf32(rb1.y); p[2]=f2tf32(rb1.z); p[3]=f2tf32(rb1.w);
    }
    __syncthreads();

    const int NC = K / GBK;
    for (int c = 0; c < NC; c++) {
        int p = c & 1;
        bool more = (c + 1 < NC);

        // ---- prefetch next chunk's globals (overlaps with MMA below) ----
        if (more) {
            int ko = (c + 1) * GBK;
            ra0 = *(const float4*)(Arow0 + ko);
            ra1 = *(const float4*)(Arow1 + ko);
            rb0 = *(const float4*)(Wrow0 + (size_t)ko * N);
            rb1 = *(const float4*)(Wrow1 + (size_t)ko * N);
        }

        // ---- MMAs on current buffer ----
        const uint32_t* AsP = As[p];
        const uint32_t* BsP = Bs[p];
        #pragma unroll
        for (int ks = 0; ks < 2; ks++) {
            int k8 = ks * 8;
            uint32_t a[4][4], b[4][2];
            #pragma unroll
            for (int mt = 0; mt < 4; mt++) {
                int r = wm + mt * 16 + lq;
                a[mt][0] = AsP[r * APITCH + k8 + lr];
                a[mt][1] = AsP[(r + 8) * APITCH + k8 + lr];
                a[mt][2] = AsP[r * APITCH + k8 + lr + 4];
                a[mt][3] = AsP[(r + 8) * APITCH + k8 + lr + 4];
            }
            #pragma unroll
            for (int nt = 0; nt < 4; nt++) {
                int cn = wn + nt * 8 + lq;
                b[nt][0] = BsP[(k8 + lr) * BPITCH + cn];
                b[nt][1] = BsP[(k8 + 4 + lr) * BPITCH + cn];
            }
            #pragma unroll
            for (int mt = 0; mt < 4; mt++)
                #pragma unroll
                for (int nt = 0; nt < 4; nt++)
                    mma_tf32(acc[mt][nt], a[mt], b[nt], acc[mt][nt]);
        }

        // ---- stage next chunk into the other buffer ----
        if (more) {
            uint32_t* q;
            q = &As[1 - p][am0 * APITCH + ac0];
            q[0]=f2tf32(ra0.x); q[1]=f2tf32(ra0.y); q[2]=f2tf32(ra0.z); q[3]=f2tf32(ra0.w);
            q = &As[1 - p][am1 * APITCH + ac1];
            q[0]=f2tf32(ra1.x); q[1]=f2tf32(ra1.y); q[2]=f2tf32(ra1.z); q[3]=f2tf32(ra1.w);
            q = &Bs[1 - p][bk0 * BPITCH + bn0];
            q[0]=f2tf32(rb0.x); q[1]=f2tf32(rb0.y); q[2]=f2tf32(rb0.z); q[3]=f2tf32(rb0.w);
            q = &Bs[1 - p][bk1 * BPITCH + bn1];
            q[0]=f2tf32(rb1.x); q[1]=f2tf32(rb1.y); q[2]=f2tf32(rb1.z); q[3]=f2tf32(rb1.w);
        }
        __syncthreads();
    }

    // ---- epilogue ----
    #pragma unroll
    for (int mt = 0; mt < 4; mt++) {
        int row0 = m0 + wm + mt * 16 + lq;
        #pragma unroll
        for (int nt = 0; nt < 4; nt++) {
            int col = n0 + wn + nt * 8 + lr * 2;
            #pragma unroll
            for (int half = 0; half < 2; half++) {
                int row = row0 + half * 8;
                float v0 = acc[mt][nt][half * 2 + 0];
                float v1 = acc[mt][nt][half * 2 + 1];
                if (bias) {
                    v0 += __ldg(bias + col);
                    v1 += __ldg(bias + col + 1);
                }
                if (do_gelu) {
                    v0 = 0.5f * v0 * (1.0f + erff(v0 * 0.70710678118654752f));
                    v1 = 0.5f * v1 * (1.0f + erff(v1 * 0.70710678118654752f));
                }
                if (res) {
                    const float2 rr = *(const float2*)(res + (size_t)row * N + col);
                    v0 += rr.x; v1 += rr.y;
                }
                float2 o2; o2.x = v0; o2.y = v1;
                *(float2*)(out + (size_t)row * N + col) = o2;
            }
        }
    }
}

// ============================== fused flash attention (fp32) ==============================
#define ATTN_SMEM ((3 * 64 * 68 + 64 * 64) * 4)

__global__ void __launch_bounds__(256)
attn_kernel(const float* __restrict__ q, const float* __restrict__ k,
            const float* __restrict__ v, float* __restrict__ o) {
    extern __shared__ float sm[];
    float* Qt = sm;
    float* Kt = sm + 64 * 68;
    float* Pt = sm + 2 * 64 * 68;
    float* Vs = sm + 3 * 64 * 68;

    int tid = threadIdx.x;
    int tx = tid & 15, ty = tid >> 4;
    int qt0 = blockIdx.x * 64;
    int h = blockIdx.y, b = blockIdx.z;
    size_t base = ((size_t)b * TT) * CC + (size_t)h * DD;

    #pragma unroll
    for (int i = 0; i < 16; i++) {
        int idx = tid + i * 256;
        int r = idx >> 6, d = idx & 63;
        Qt[d * 68 + r] = q[base + (size_t)(qt0 + r) * CC + d] * 0.125f;
    }

    float m[4], l[4], accO[4][4];
    #pragma unroll
    for (int i = 0; i < 4; i++) {
        m[i] = -1e30f; l[i] = 0.f;
        #pragma unroll
        for (int j = 0; j < 4; j++) accO[i][j] = 0.f;
    }

    for (int s0 = 0; s0 < TT; s0 += 64) {
        __syncthreads();
        #pragma unroll
        for (int i = 0; i < 16; i++) {
            int idx = tid + i * 256;
            int r = idx >> 6, d = idx & 63;
            Kt[d * 68 + r] = k[base + (size_t)(s0 + r) * CC + d];
            Vs[r * 64 + d] = v[base + (size_t)(s0 + r) * CC + d];
        }
        __syncthreads();

        float s[4][4];
        #pragma unroll
        for (int i = 0; i < 4; i++)
            #pragma unroll
            for (int j = 0; j < 4; j++) s[i][j] = 0.f;
        #pragma unroll 8
        for (int d = 0; d < 64; d++) {
            float4 a  = *(const float4*)&Qt[d * 68 + ty * 4];
            float4 bb = *(const float4*)&Kt[d * 68 + tx * 4];
            s[0][0] += a.x*bb.x; s[0][1] += a.x*bb.y; s[0][2] += a.x*bb.z; s[0][3] += a.x*bb.w;
            s[1][0] += a.y*bb.x; s[1][1] += a.y*bb.y; s[1][2] += a.y*bb.z; s[1][3] += a.y*bb.w;
            s[2][0] += a.z*bb.x; s[2][1] += a.z*bb.y; s[2][2] += a.z*bb.z; s[2][3] += a.z*bb.w;
            s[3][0] += a.w*bb.x; s[3][1] += a.w*bb.y; s[3][2] += a.w*bb.z; s[3][3] += a.w*bb.w;
        }

        #pragma unroll
        for (int i = 0; i < 4; i++) {
            float rm = fmaxf(fmaxf(s[i][0], s[i][1]), fmaxf(s[i][2], s[i][3]));
            rm = fmaxf(rm, __shfl_xor_sync(0xffffffffu, rm, 1));
            rm = fmaxf(rm, __shfl_xor_sync(0xffffffffu, rm, 2));
            rm = fmaxf(rm, __shfl_xor_sync(0xffffffffu, rm, 4));
            rm = fmaxf(rm, __shfl_xor_sync(0xffffffffu, rm, 8));
            float mn = fmaxf(m[i], rm);
            float corr = expf(m[i] - mn);
            m[i] = mn;
            float rs = 0.f;
            #pragma unroll
            for (int j = 0; j < 4; j++) {
                float p = expf(s[i][j] - mn);
                s[i][j] = p;
                rs += p;
            }
            rs += __shfl_xor_sync(0xffffffffu, rs, 1);
            rs += __shfl_xor_sync(0xffffffffu, rs, 2);
            rs += __shfl_xor_sync(0xffffffffu, rs, 4);
            rs += __shfl_xor_sync(0xffffffffu, rs, 8);
            l[i] = l[i] * corr + rs;
            #pragma unroll
            for (int j = 0; j < 4; j++) accO[i][j] *= corr;
        }

        #pragma unroll
        for (int i = 0; i < 4; i++)
            #pragma unroll
            for (int j = 0; j < 4; j++)
                Pt[(tx * 4 + j) * 68 + ty * 4 + i] = s[i][j];
        __syncthreads();

        #pragma unroll 8
        for (int j = 0; j < 64; j++) {
            float4 p  = *(const float4*)&Pt[j * 68 + ty * 4];
            float4 vv = *(const float4*)&Vs[j * 64 + tx * 4];
            accO[0][0] += p.x*vv.x; accO[0][1] += p.x*vv.y; accO[0][2] += p.x*vv.z; accO[0][3] += p.x*vv.w;
            accO[1][0] += p.y*vv.x; accO[1][1] += p.y*vv.y; accO[1][2] += p.y*vv.z; accO[1][3] += p.y*vv.w;
            accO[2][0] += p.z*vv.x; accO[2][1] += p.z*vv.y; accO[2][2] += p.z*vv.z; accO[2][3] += p.z*vv.w;
            accO[3][0] += p.w*vv.x; accO[3][1] += p.w*vv.y; accO[3][2] += p.w*vv.z; accO[3][3] += p.w*vv.w;
        }
    }

    #pragma unroll
    for (int i = 0; i < 4; i++) {
        float invl = 1.0f / l[i];
        int t = qt0 + ty * 4 + i;
        #pragma unroll
        for (int j = 0; j < 4; j++)
            o[base + (size_t)t * CC + tx * 4 + j] = accO[i][j] * invl;
    }
}

// ============================== launcher ==============================
extern "C" void kernel_launch(void* const* d_in, const int* in_sizes, int n_in,
                              void* d_out, int out_size) {
    (void)in_sizes; (void)n_in; (void)out_size;

    const int*   src     = (const int*)  d_in[0];
    const float* src_emb = (const float*)d_in[1];
    const float* pos_emb = (const float*)d_in[2];
    const float* ln1_w   = (const float*)d_in[3];
    const float* ln1_b   = (const float*)d_in[4];
    const float* wq      = (const float*)d_in[5];
    const float* bq      = (const float*)d_in[6];
    const float* wk      = (const float*)d_in[7];
    const float* bk      = (const float*)d_in[8];
    const float* wv      = (const float*)d_in[9];
    const float* bv      = (const float*)d_in[10];
    const float* wo      = (const float*)d_in[11];
    const float* bo      = (const float*)d_in[12];
    const float* ln2_w   = (const float*)d_in[13];
    const float* ln2_b   = (const float*)d_in[14];
    const float* w1      = (const float*)d_in[15];
    const float* b1      = (const float*)d_in[16];
    const float* w2      = (const float*)d_in[17];
    const float* b2      = (const float*)d_in[18];
    const float* lnf_w   = (const float*)d_in[19];
    const float* lnf_b   = (const float*)d_in[20];
    const float* head_w  = (const float*)d_in[21];

    float *xb, *hb, *qb, *kb, *vb, *ob, *fb;
    cudaGetSymbolAddress((void**)&xb, g_x);
    cudaGetSymbolAddress((void**)&hb, g_h);
    cudaGetSymbolAddress((void**)&qb, g_q);
    cudaGetSymbolAddress((void**)&kb, g_k);
    cudaGetSymbolAddress((void**)&vb, g_v);
    cudaGetSymbolAddress((void**)&ob, g_o);
    cudaGetSymbolAddress((void**)&fb, g_ff);

    cudaFuncSetAttribute(attn_kernel, cudaFuncAttributeMaxDynamicSharedMemorySize, ATTN_SMEM);

    embed_kernel<<<MT, 256>>>(src, src_emb, pos_emb, xb);

    dim3 gC(CC / GBN, MT / GBM);    // (8, 32)
    dim3 gF(FFD / GBN, MT / GBM);   // (32, 32)
    dim3 gH(VV / GBN, MT / GBM);    // (250, 32)
    dim3 gA(TT / 64, HH, BSZ);

    for (int l = 0; l < LL; l++) {
        size_t wOff  = (size_t)l * CC * CC;
        size_t w1Off = (size_t)l * CC * FFD;
        size_t w2Off = (size_t)l * FFD * CC;

        ln_kernel<<<MT, 256>>>(xb, ln1_w + l * CC, ln1_b + l * CC, hb);
        mma_gemm<<<gC, 256>>>(hb, wq + wOff, bq + l * CC, nullptr, qb, MT, CC, CC, 0);
        mma_gemm<<<gC, 256>>>(hb, wk + wOff, bk + l * CC, nullptr, kb, MT, CC, CC, 0);
        mma_gemm<<<gC, 256>>>(hb, wv + wOff, bv + l * CC, nullptr, vb, MT, CC, CC, 0);

        attn_kernel<<<gA, 256, ATTN_SMEM>>>(qb, kb, vb, ob);

        mma_gemm<<<gC, 256>>>(ob, wo + wOff, bo + l * CC, xb, xb, MT, CC, CC, 0);

        ln_kernel<<<MT, 256>>>(xb, ln2_w + l * CC, ln2_b + l * CC, hb);
        mma_gemm<<<gF, 256>>>(hb, w1 + w1Off, b1 + l * FFD, nullptr, fb, MT, FFD, CC, 1);
        mma_gemm<<<gC, 256>>>(fb, w2 + w2Off, b2 + l * CC, xb, xb, MT, CC, FFD, 0);
    }

    ln_kernel<<<MT, 256>>>(xb, lnf_w, lnf_b, hb);
    mma_gemm<<<gH, 256>>>(hb, head_w, nullptr, nullptr, (float*)d_out, MT, VV, CC, 0);
}

// round 5
// speedup vs baseline: 2.4605x; 1.1031x over previous
#include <cuda_runtime.h>
#include <math.h>
#include <stdint.h>

// Problem constants
#define BSZ 2
#define TT  2048
#define CC  1024
#define HH  16
#define LL  6
#define VV  32000
#define DD  64
#define FFD 4096
#define MT  (BSZ*TT)   // 4096 rows

// -------- scratch (device globals: allocation-free per harness rules) --------
__device__ float g_x [MT*CC];
__device__ float g_h [MT*CC];
__device__ float g_q [MT*CC];
__device__ float g_k [MT*CC];
__device__ float g_v [MT*CC];
__device__ float g_o [MT*CC];
__device__ float g_ff[(size_t)MT*FFD];
__device__ float g_wT[(size_t)VV*CC];   // tf32-rounded weight staging (max 32000x1024)

// ============================== helpers ==============================
__device__ __forceinline__ uint32_t f2tf32(float x) {
    uint32_t r; asm("cvt.rna.tf32.f32 %0, %1;" : "=r"(r) : "f"(x)); return r;
}
__device__ __forceinline__ float f2tf32f(float x) {
    return __uint_as_float(f2tf32(x));
}

// m16n8k8 tf32 mma (row.col), fp32 accumulate — sm_80+ instruction, no 'a' feature.
__device__ __forceinline__ void mma_tf32(float* d, const uint32_t* a, const uint32_t* b,
                                         const float* c) {
    asm volatile(
        "mma.sync.aligned.m16n8k8.row.col.f32.tf32.tf32.f32 "
        "{%0,%1,%2,%3}, {%4,%5,%6,%7}, {%8,%9}, {%10,%11,%12,%13};"
        : "=f"(d[0]), "=f"(d[1]), "=f"(d[2]), "=f"(d[3])
        : "r"(a[0]), "r"(a[1]), "r"(a[2]), "r"(a[3]),
          "r"(b[0]), "r"(b[1]),
          "f"(c[0]), "f"(c[1]), "f"(c[2]), "f"(c[3]));
}

__device__ __forceinline__ void ldmatrix_x4(uint32_t* r, uint32_t addr) {
    asm volatile("ldmatrix.sync.aligned.m8n8.x4.shared.b16 {%0,%1,%2,%3}, [%4];"
                 : "=r"(r[0]), "=r"(r[1]), "=r"(r[2]), "=r"(r[3]) : "r"(addr));
}

#define CP_ASYNC16(dst, src) \
    asm volatile("cp.async.cg.shared.global [%0], [%1], 16;" :: "r"(dst), "l"(src) : "memory")
#define CP_COMMIT() asm volatile("cp.async.commit_group;" ::: "memory")
#define CP_WAIT2()  asm volatile("cp.async.wait_group 2;" ::: "memory")

// ============================== tf32 rounding (weights) ==============================
__global__ void round_tf32_kernel(const float* __restrict__ in, float* __restrict__ out) {
    size_t i = ((size_t)blockIdx.x * 256 + threadIdx.x) * 4;
    float4 v = *(const float4*)(in + i);
    uint4 r;
    r.x = f2tf32(v.x); r.y = f2tf32(v.y); r.z = f2tf32(v.z); r.w = f2tf32(v.w);
    *(uint4*)(out + i) = r;
}

// ============================== embedding ==============================
__global__ void embed_kernel(const int* __restrict__ src,
                             const float* __restrict__ emb,
                             const float* __restrict__ pos,
                             float* __restrict__ out) {
    int row = blockIdx.x;
    int tok = src[row];
    int t   = row & (TT - 1);
    float4 e = ((const float4*)(emb + (size_t)tok * CC))[threadIdx.x];
    float4 p = ((const float4*)(pos + (size_t)t * CC))[threadIdx.x];
    float4 r;
    r.x = e.x + p.x; r.y = e.y + p.y; r.z = e.z + p.z; r.w = e.w + p.w;
    ((float4*)(out + (size_t)row * CC))[threadIdx.x] = r;
}

// ============================== layernorm (tf32-rounded output) ==============================
__global__ void ln_kernel(const float* __restrict__ x,
                          const float* __restrict__ w,
                          const float* __restrict__ b,
                          float* __restrict__ out) {
    int row = blockIdx.x;
    int tid = threadIdx.x;
    __shared__ float red[8];
    __shared__ float sval;

    float4 v = ((const float4*)(x + (size_t)row * CC))[tid];
    float s = v.x + v.y + v.z + v.w;
    #pragma unroll
    for (int o = 16; o; o >>= 1) s += __shfl_xor_sync(0xffffffffu, s, o);
    if ((tid & 31) == 0) red[tid >> 5] = s;
    __syncthreads();
    if (tid == 0) {
        float t = 0.f;
        #pragma unroll
        for (int i = 0; i < 8; i++) t += red[i];
        sval = t * (1.0f / CC);
    }
    __syncthreads();
    float mu = sval;
    float dx = v.x - mu, dy = v.y - mu, dz = v.z - mu, dw = v.w - mu;
    float ss = dx*dx + dy*dy + dz*dz + dw*dw;
    #pragma unroll
    for (int o = 16; o; o >>= 1) ss += __shfl_xor_sync(0xffffffffu, ss, o);
    if ((tid & 31) == 0) red[tid >> 5] = ss;
    __syncthreads();
    if (tid == 0) {
        float t = 0.f;
        #pragma unroll
        for (int i = 0; i < 8; i++) t += red[i];
        sval = rsqrtf(t * (1.0f / CC) + 1e-5f);
    }
    __syncthreads();
    float inv = sval;
    float4 w4 = ((const float4*)w)[tid];
    float4 b4 = ((const float4*)b)[tid];
    float4 r;
    r.x = f2tf32f(dx * inv * w4.x + b4.x);
    r.y = f2tf32f(dy * inv * w4.y + b4.y);
    r.z = f2tf32f(dz * inv * w4.z + b4.z);
    r.w = f2tf32f(dw * inv * w4.w + b4.w);
    ((float4*)(out + (size_t)row * CC))[tid] = r;
}

// ============================== tf32 tensor-core GEMM (cp.async 4-stage) ==============================
// out[M,N] = A[M,K] @ W[K,N] (+bias) (gelu?) (+res) (round_out?)
// A and W must already be tf32-rounded (MMA truncation is then exact).
// CTA: 128x128x16, 8 warps in 2(m) x 4(n), each warp 64x32 = 4x4 m16n8k8 tiles.
#define GBM 128
#define GBN 128
#define GBK 16
#define APITCH 20     // As[m][k] word pitch: ldmatrix rows conflict-free, 16B aligned
#define BPITCH 136    // Bs[k][n] word pitch: b-frag bank = 8*lr+lq -> conflict-free
#define ASTAGE (GBM * APITCH * 4)        // 10240 B
#define BSTAGE (GBK * BPITCH * 4)        // 8704 B
#define NSTAGES 4
#define GEMM_SMEM (NSTAGES * (ASTAGE + BSTAGE))   // 75776 B

__global__ void __launch_bounds__(256, 2)
mma_gemm(const float* __restrict__ A, const float* __restrict__ W,
         const float* __restrict__ bias, const float* __restrict__ res,
         float* __restrict__ out, int M, int N, int K, int do_gelu, int round_out) {
    extern __shared__ char smch[];
    uint32_t smemu = (uint32_t)__cvta_generic_to_shared(smch);

    int tid  = threadIdx.x;
    int lane = tid & 31;
    int wid  = tid >> 5;
    int wm   = (wid >> 2) * 64;     // warp m offset (0 or 64)
    int wn   = (wid & 3) * 32;      // warp n offset (0,32,64,96)
    int m0 = blockIdx.y * GBM, n0 = blockIdx.x * GBN;

    int lq = lane >> 2;             // 0..7
    int lr = lane & 3;              // 0..3

    // ldmatrix per-lane source row/col within the A tile
    int lrow = (lane & 7) + ((lane >> 3) & 1) * 8;  // 0..15
    int lcol = (lane >> 4) * 4;                     // 0 or 4

    // copy-task coordinates (4x 16B cp.async per thread per chunk)
    int arow = tid >> 1, ac0 = (tid & 1);           // A: 128 rows x {c16, c16+2}
    int brow = tid >> 5, bc = tid & 31;             // B: rows {r, r+8} x 32 cols16

    const float* Asrc0 = A + (size_t)(m0 + arow) * K + ac0 * 4;
    const float* Asrc1 = A + (size_t)(m0 + arow) * K + (ac0 + 2) * 4;
    const float* Bsrc0 = W + (size_t)brow * N + n0 + bc * 4;
    const float* Bsrc1 = W + (size_t)(brow + 8) * N + n0 + bc * 4;

    uint32_t adst0 = smemu + arow * (APITCH * 4) + ac0 * 16;
    uint32_t adst1 = adst0 + 32;
    uint32_t bbase = smemu + NSTAGES * ASTAGE;
    uint32_t bdst0 = bbase + brow * (BPITCH * 4) + bc * 16;
    uint32_t bdst1 = bdst0 + 8 * (BPITCH * 4);

    float acc[4][4][4];
    #pragma unroll
    for (int i = 0; i < 4; i++)
        #pragma unroll
        for (int j = 0; j < 4; j++)
            #pragma unroll
            for (int r = 0; r < 4; r++) acc[i][j][r] = 0.f;

    const int NC = K / GBK;

    // ---- prologue: stages 0..2 ----
    #pragma unroll
    for (int s = 0; s < NSTAGES - 1; s++) {
        size_t ko = (size_t)s * GBK;
        CP_ASYNC16(adst0 + s * ASTAGE, Asrc0 + ko);
        CP_ASYNC16(adst1 + s * ASTAGE, Asrc1 + ko);
        CP_ASYNC16(bdst0 + s * BSTAGE, Bsrc0 + ko * N);
        CP_ASYNC16(bdst1 + s * BSTAGE, Bsrc1 + ko * N);
        CP_COMMIT();
    }

    for (int c = 0; c < NC; c++) {
        CP_WAIT2();
        __syncthreads();

        int st = c & (NSTAGES - 1);
        uint32_t aST = smemu + st * ASTAGE;
        const uint32_t* BsP = (const uint32_t*)(smch + NSTAGES * ASTAGE + st * BSTAGE);

        #pragma unroll
        for (int ks = 0; ks < 2; ks++) {
            int k8 = ks * 8;
            uint32_t a[4][4], b[4][2];
            #pragma unroll
            for (int mt = 0; mt < 4; mt++) {
                uint32_t addr = aST + (((wm + mt * 16 + lrow) * APITCH) + k8 + lcol) * 4;
                ldmatrix_x4(a[mt], addr);
            }
            #pragma unroll
            for (int nt = 0; nt < 4; nt++) {
                int cn = wn + nt * 8 + lq;
                b[nt][0] = BsP[(k8 + lr) * BPITCH + cn];
                b[nt][1] = BsP[(k8 + 4 + lr) * BPITCH + cn];
            }
            #pragma unroll
            for (int mt = 0; mt < 4; mt++)
                #pragma unroll
                for (int nt = 0; nt < 4; nt++)
                    mma_tf32(acc[mt][nt], a[mt], b[nt], acc[mt][nt]);
        }

        // issue chunk c+3 into stage (c+3)%4 (read last at chunk c-1; barrier above protects it)
        int nc = c + NSTAGES - 1;
        if (nc < NC) {
            int s = nc & (NSTAGES - 1);
            size_t ko = (size_t)nc * GBK;
            CP_ASYNC16(adst0 + s * ASTAGE, Asrc0 + ko);
            CP_ASYNC16(adst1 + s * ASTAGE, Asrc1 + ko);
            CP_ASYNC16(bdst0 + s * BSTAGE, Bsrc0 + ko * N);
            CP_ASYNC16(bdst1 + s * BSTAGE, Bsrc1 + ko * N);
        }
        CP_COMMIT();
    }

    // ---- epilogue ----
    #pragma unroll
    for (int mt = 0; mt < 4; mt++) {
        int row0 = m0 + wm + mt * 16 + lq;
        #pragma unroll
        for (int nt = 0; nt < 4; nt++) {
            int col = n0 + wn + nt * 8 + lr * 2;
            #pragma unroll
            for (int half = 0; half < 2; half++) {
                int row = row0 + half * 8;
                float v0 = acc[mt][nt][half * 2 + 0];
                float v1 = acc[mt][nt][half * 2 + 1];
                if (bias) {
                    v0 += __ldg(bias + col);
                    v1 += __ldg(bias + col + 1);
                }
                if (do_gelu) {
                    v0 = 0.5f * v0 * (1.0f + erff(v0 * 0.70710678118654752f));
                    v1 = 0.5f * v1 * (1.0f + erff(v1 * 0.70710678118654752f));
                }
                if (res) {
                    const float2 rr = *(const float2*)(res + (size_t)row * N + col);
                    v0 += rr.x; v1 += rr.y;
                }
                if (round_out) { v0 = f2tf32f(v0); v1 = f2tf32f(v1); }
                float2 o2; o2.x = v0; o2.y = v1;
                *(float2*)(out + (size_t)row * N + col) = o2;
            }
        }
    }
}

// ============================== fused flash attention (fp32, tf32-rounded output) ==============================
#define ATTN_SMEM ((3 * 64 * 68 + 64 * 64) * 4)

__global__ void __launch_bounds__(256)
attn_kernel(const float* __restrict__ q, const float* __restrict__ k,
            const float* __restrict__ v, float* __restrict__ o) {
    extern __shared__ float sm[];
    float* Qt = sm;
    float* Kt = sm + 64 * 68;
    float* Pt = sm + 2 * 64 * 68;
    float* Vs = sm + 3 * 64 * 68;

    int tid = threadIdx.x;
    int tx = tid & 15, ty = tid >> 4;
    int qt0 = blockIdx.x * 64;
    int h = blockIdx.y, b = blockIdx.z;
    size_t base = ((size_t)b * TT) * CC + (size_t)h * DD;

    #pragma unroll
    for (int i = 0; i < 16; i++) {
        int idx = tid + i * 256;
        int r = idx >> 6, d = idx & 63;
        Qt[d * 68 + r] = q[base + (size_t)(qt0 + r) * CC + d] * 0.125f;
    }

    float m[4], l[4], accO[4][4];
    #pragma unroll
    for (int i = 0; i < 4; i++) {
        m[i] = -1e30f; l[i] = 0.f;
        #pragma unroll
        for (int j = 0; j < 4; j++) accO[i][j] = 0.f;
    }

    for (int s0 = 0; s0 < TT; s0 += 64) {
        __syncthreads();
        #pragma unroll
        for (int i = 0; i < 16; i++) {
            int idx = tid + i * 256;
            int r = idx >> 6, d = idx & 63;
            Kt[d * 68 + r] = k[base + (size_t)(s0 + r) * CC + d];
            Vs[r * 64 + d] = v[base + (size_t)(s0 + r) * CC + d];
        }
        __syncthreads();

        float s[4][4];
        #pragma unroll
        for (int i = 0; i < 4; i++)
            #pragma unroll
            for (int j = 0; j < 4; j++) s[i][j] = 0.f;
        #pragma unroll 8
        for (int d = 0; d < 64; d++) {
            float4 a  = *(const float4*)&Qt[d * 68 + ty * 4];
            float4 bb = *(const float4*)&Kt[d * 68 + tx * 4];
            s[0][0] += a.x*bb.x; s[0][1] += a.x*bb.y; s[0][2] += a.x*bb.z; s[0][3] += a.x*bb.w;
            s[1][0] += a.y*bb.x; s[1][1] += a.y*bb.y; s[1][2] += a.y*bb.z; s[1][3] += a.y*bb.w;
            s[2][0] += a.z*bb.x; s[2][1] += a.z*bb.y; s[2][2] += a.z*bb.z; s[2][3] += a.z*bb.w;
            s[3][0] += a.w*bb.x; s[3][1] += a.w*bb.y; s[3][2] += a.w*bb.z; s[3][3] += a.w*bb.w;
        }

        #pragma unroll
        for (int i = 0; i < 4; i++) {
            float rm = fmaxf(fmaxf(s[i][0], s[i][1]), fmaxf(s[i][2], s[i][3]));
            rm = fmaxf(rm, __shfl_xor_sync(0xffffffffu, rm, 1));
            rm = fmaxf(rm, __shfl_xor_sync(0xffffffffu, rm, 2));
            rm = fmaxf(rm, __shfl_xor_sync(0xffffffffu, rm, 4));
            rm = fmaxf(rm, __shfl_xor_sync(0xffffffffu, rm, 8));
            float mn = fmaxf(m[i], rm);
            float corr = expf(m[i] - mn);
            m[i] = mn;
            float rs = 0.f;
            #pragma unroll
            for (int j = 0; j < 4; j++) {
                float p = expf(s[i][j] - mn);
                s[i][j] = p;
                rs += p;
            }
            rs += __shfl_xor_sync(0xffffffffu, rs, 1);
            rs += __shfl_xor_sync(0xffffffffu, rs, 2);
            rs += __shfl_xor_sync(0xffffffffu, rs, 4);
            rs += __shfl_xor_sync(0xffffffffu, rs, 8);
            l[i] = l[i] * corr + rs;
            #pragma unroll
            for (int j = 0; j < 4; j++) accO[i][j] *= corr;
        }

        #pragma unroll
        for (int i = 0; i < 4; i++)
            #pragma unroll
            for (int j = 0; j < 4; j++)
                Pt[(tx * 4 + j) * 68 + ty * 4 + i] = s[i][j];
        __syncthreads();

        #pragma unroll 8
        for (int j = 0; j < 64; j++) {
            float4 p  = *(const float4*)&Pt[j * 68 + ty * 4];
            float4 vv = *(const float4*)&Vs[j * 64 + tx * 4];
            accO[0][0] += p.x*vv.x; accO[0][1] += p.x*vv.y; accO[0][2] += p.x*vv.z; accO[0][3] += p.x*vv.w;
            accO[1][0] += p.y*vv.x; accO[1][1] += p.y*vv.y; accO[1][2] += p.y*vv.z; accO[1][3] += p.y*vv.w;
            accO[2][0] += p.z*vv.x; accO[2][1] += p.z*vv.y; accO[2][2] += p.z*vv.z; accO[2][3] += p.z*vv.w;
            accO[3][0] += p.w*vv.x; accO[3][1] += p.w*vv.y; accO[3][2] += p.w*vv.z; accO[3][3] += p.w*vv.w;
        }
    }

    #pragma unroll
    for (int i = 0; i < 4; i++) {
        float invl = 1.0f / l[i];
        int t = qt0 + ty * 4 + i;
        #pragma unroll
        for (int j = 0; j < 4; j++)
            o[base + (size_t)t * CC + tx * 4 + j] = f2tf32f(accO[i][j] * invl);
    }
}

// ============================== launcher ==============================
extern "C" void kernel_launch(void* const* d_in, const int* in_sizes, int n_in,
                              void* d_out, int out_size) {
    (void)in_sizes; (void)n_in; (void)out_size;

    const int*   src     = (const int*)  d_in[0];
    const float* src_emb = (const float*)d_in[1];
    const float* pos_emb = (const float*)d_in[2];
    const float* ln1_w   = (const float*)d_in[3];
    const float* ln1_b   = (const float*)d_in[4];
    const float* wq      = (const float*)d_in[5];
    const float* bq      = (const float*)d_in[6];
    const float* wk      = (const float*)d_in[7];
    const float* bk      = (const float*)d_in[8];
    const float* wv      = (const float*)d_in[9];
    const float* bv      = (const float*)d_in[10];
    const float* wo      = (const float*)d_in[11];
    const float* bo      = (const float*)d_in[12];
    const float* ln2_w   = (const float*)d_in[13];
    const float* ln2_b   = (const float*)d_in[14];
    const float* w1      = (const float*)d_in[15];
    const float* b1      = (const float*)d_in[16];
    const float* w2      = (const float*)d_in[17];
    const float* b2      = (const float*)d_in[18];
    const float* lnf_w   = (const float*)d_in[19];
    const float* lnf_b   = (const float*)d_in[20];
    const float* head_w  = (const float*)d_in[21];

    float *xb, *hb, *qb, *kb, *vb, *ob, *fb, *wT;
    cudaGetSymbolAddress((void**)&xb, g_x);
    cudaGetSymbolAddress((void**)&hb, g_h);
    cudaGetSymbolAddress((void**)&qb, g_q);
    cudaGetSymbolAddress((void**)&kb, g_k);
    cudaGetSymbolAddress((void**)&vb, g_v);
    cudaGetSymbolAddress((void**)&ob, g_o);
    cudaGetSymbolAddress((void**)&fb, g_ff);
    cudaGetSymbolAddress((void**)&wT, g_wT);

    cudaFuncSetAttribute(attn_kernel, cudaFuncAttributeMaxDynamicSharedMemorySize, ATTN_SMEM);
    cudaFuncSetAttribute(mma_gemm, cudaFuncAttributeMaxDynamicSharedMemorySize, GEMM_SMEM);

    embed_kernel<<<MT, 256>>>(src, src_emb, pos_emb, xb);

    dim3 gC(CC / GBN, MT / GBM);    // (8, 32)
    dim3 gF(FFD / GBN, MT / GBM);   // (32, 32)
    dim3 gH(VV / GBN, MT / GBM);    // (250, 32)
    dim3 gA(TT / 64, HH, BSZ);

    const int RB_CC = (CC * CC) / 1024;        // 1024 blocks
    const int RB_FF = (CC * FFD) / 1024;       // 4096 blocks
    const int RB_HD = (VV * CC) / 1024;        // 32000 blocks

    for (int l = 0; l < LL; l++) {
        size_t wOff  = (size_t)l * CC * CC;
        size_t w1Off = (size_t)l * CC * FFD;
        size_t w2Off = (size_t)l * FFD * CC;

        ln_kernel<<<MT, 256>>>(xb, ln1_w + l * CC, ln1_b + l * CC, hb);

        round_tf32_kernel<<<RB_CC, 256>>>(wq + wOff, wT);
        mma_gemm<<<gC, 256, GEMM_SMEM>>>(hb, wT, bq + l * CC, nullptr, qb, MT, CC, CC, 0, 0);
        round_tf32_kernel<<<RB_CC, 256>>>(wk + wOff, wT);
        mma_gemm<<<gC, 256, GEMM_SMEM>>>(hb, wT, bk + l * CC, nullptr, kb, MT, CC, CC, 0, 0);
        round_tf32_kernel<<<RB_CC, 256>>>(wv + wOff, wT);
        mma_gemm<<<gC, 256, GEMM_SMEM>>>(hb, wT, bv + l * CC, nullptr, vb, MT, CC, CC, 0, 0);

        attn_kernel<<<gA, 256, ATTN_SMEM>>>(qb, kb, vb, ob);

        round_tf32_kernel<<<RB_CC, 256>>>(wo + wOff, wT);
        mma_gemm<<<gC, 256, GEMM_SMEM>>>(ob, wT, bo + l * CC, xb, xb, MT, CC, CC, 0, 0);

        ln_kernel<<<MT, 256>>>(xb, ln2_w + l * CC, ln2_b + l * CC, hb);

        round_tf32_kernel<<<RB_FF, 256>>>(w1 + w1Off, wT);
        mma_gemm<<<gF, 256, GEMM_SMEM>>>(hb, wT, b1 + l * FFD, nullptr, fb, MT, FFD, CC, 1, 1);
        round_tf32_kernel<<<RB_FF, 256>>>(w2 + w2Off, wT);
        mma_gemm<<<gC, 256, GEMM_SMEM>>>(fb, wT, b2 + l * CC, xb, xb, MT, CC, FFD, 0, 0);
    }

    ln_kernel<<<MT, 256>>>(xb, lnf_w, lnf_b, hb);
    round_tf32_kernel<<<RB_HD, 256>>>(head_w, wT);
    mma_gemm<<<gH, 256, GEMM_SMEM>>>(hb, wT, nullptr, nullptr, (float*)d_out, MT, VV, CC, 0, 0);
}

// round 6
// speedup vs baseline: 3.5876x; 1.4581x over previous
#include <cuda_runtime.h>
#include <math.h>
#include <stdint.h>

// Problem constants
#define BSZ 2
#define TT  2048
#define CC  1024
#define HH  16
#define LL  6
#define VV  32000
#define DD  64
#define FFD 4096
#define MT  (BSZ*TT)   // 4096 rows

// -------- scratch (device globals: allocation-free per harness rules) --------
__device__ float g_x [MT*CC];
__device__ float g_h [MT*CC];
__device__ float g_q [MT*CC];
__device__ float g_k [MT*CC];
__device__ float g_v [MT*CC];
__device__ float g_o [MT*CC];
__device__ float g_ff[(size_t)MT*FFD];
__device__ float g_wT[(size_t)VV*CC];   // tf32-rounded weight staging (max 32000x1024)

// ============================== helpers ==============================
__device__ __forceinline__ uint32_t f2tf32(float x) {
    uint32_t r; asm("cvt.rna.tf32.f32 %0, %1;" : "=r"(r) : "f"(x)); return r;
}
__device__ __forceinline__ float f2tf32f(float x) {
    return __uint_as_float(f2tf32(x));
}

// m16n8k8 tf32 mma (row.col), fp32 accumulate — sm_80+ instruction, no 'a' feature.
__device__ __forceinline__ void mma_tf32(float* d, const uint32_t* a, const uint32_t* b,
                                         const float* c) {
    asm volatile(
        "mma.sync.aligned.m16n8k8.row.col.f32.tf32.tf32.f32 "
        "{%0,%1,%2,%3}, {%4,%5,%6,%7}, {%8,%9}, {%10,%11,%12,%13};"
        : "=f"(d[0]), "=f"(d[1]), "=f"(d[2]), "=f"(d[3])
        : "r"(a[0]), "r"(a[1]), "r"(a[2]), "r"(a[3]),
          "r"(b[0]), "r"(b[1]),
          "f"(c[0]), "f"(c[1]), "f"(c[2]), "f"(c[3]));
}

__device__ __forceinline__ void ldmatrix_x4(uint32_t* r, uint32_t addr) {
    asm volatile("ldmatrix.sync.aligned.m8n8.x4.shared.b16 {%0,%1,%2,%3}, [%4];"
                 : "=r"(r[0]), "=r"(r[1]), "=r"(r[2]), "=r"(r[3]) : "r"(addr));
}

#define CP_ASYNC16(dst, src) \
    asm volatile("cp.async.cg.shared.global [%0], [%1], 16;" :: "r"(dst), "l"(src) : "memory")
#define CP_COMMIT() asm volatile("cp.async.commit_group;" ::: "memory")
#define CP_WAIT2()  asm volatile("cp.async.wait_group 2;" ::: "memory")

// ============================== tf32 rounding (weights) ==============================
__global__ void round_tf32_kernel(const float* __restrict__ in, float* __restrict__ out) {
    size_t i = ((size_t)blockIdx.x * 256 + threadIdx.x) * 4;
    float4 v = *(const float4*)(in + i);
    uint4 r;
    r.x = f2tf32(v.x); r.y = f2tf32(v.y); r.z = f2tf32(v.z); r.w = f2tf32(v.w);
    *(uint4*)(out + i) = r;
}

// ============================== embedding ==============================
__global__ void embed_kernel(const int* __restrict__ src,
                             const float* __restrict__ emb,
                             const float* __restrict__ pos,
                             float* __restrict__ out) {
    int row = blockIdx.x;
    int tok = src[row];
    int t   = row & (TT - 1);
    float4 e = ((const float4*)(emb + (size_t)tok * CC))[threadIdx.x];
    float4 p = ((const float4*)(pos + (size_t)t * CC))[threadIdx.x];
    float4 r;
    r.x = e.x + p.x; r.y = e.y + p.y; r.z = e.z + p.z; r.w = e.w + p.w;
    ((float4*)(out + (size_t)row * CC))[threadIdx.x] = r;
}

// ============================== layernorm (tf32-rounded output) ==============================
__global__ void ln_kernel(const float* __restrict__ x,
                          const float* __restrict__ w,
                          const float* __restrict__ b,
                          float* __restrict__ out) {
    int row = blockIdx.x;
    int tid = threadIdx.x;
    __shared__ float red[8];
    __shared__ float sval;

    float4 v = ((const float4*)(x + (size_t)row * CC))[tid];
    float s = v.x + v.y + v.z + v.w;
    #pragma unroll
    for (int o = 16; o; o >>= 1) s += __shfl_xor_sync(0xffffffffu, s, o);
    if ((tid & 31) == 0) red[tid >> 5] = s;
    __syncthreads();
    if (tid == 0) {
        float t = 0.f;
        #pragma unroll
        for (int i = 0; i < 8; i++) t += red[i];
        sval = t * (1.0f / CC);
    }
    __syncthreads();
    float mu = sval;
    float dx = v.x - mu, dy = v.y - mu, dz = v.z - mu, dw = v.w - mu;
    float ss = dx*dx + dy*dy + dz*dz + dw*dw;
    #pragma unroll
    for (int o = 16; o; o >>= 1) ss += __shfl_xor_sync(0xffffffffu, ss, o);
    if ((tid & 31) == 0) red[tid >> 5] = ss;
    __syncthreads();
    if (tid == 0) {
        float t = 0.f;
        #pragma unroll
        for (int i = 0; i < 8; i++) t += red[i];
        sval = rsqrtf(t * (1.0f / CC) + 1e-5f);
    }
    __syncthreads();
    float inv = sval;
    float4 w4 = ((const float4*)w)[tid];
    float4 b4 = ((const float4*)b)[tid];
    float4 r;
    r.x = f2tf32f(dx * inv * w4.x + b4.x);
    r.y = f2tf32f(dy * inv * w4.y + b4.y);
    r.z = f2tf32f(dz * inv * w4.z + b4.z);
    r.w = f2tf32f(dw * inv * w4.w + b4.w);
    ((float4*)(out + (size_t)row * CC))[tid] = r;
}

// ============================== tf32 tensor-core GEMM (cp.async 4-stage) ==============================
#define GBM 128
#define GBN 128
#define GBK 16
#define APITCH 20
#define BPITCH 136
#define ASTAGE (GBM * APITCH * 4)
#define BSTAGE (GBK * BPITCH * 4)
#define NSTAGES 4
#define GEMM_SMEM (NSTAGES * (ASTAGE + BSTAGE))   // 75776 B

__global__ void __launch_bounds__(256, 2)
mma_gemm(const float* __restrict__ A, const float* __restrict__ W,
         const float* __restrict__ bias, const float* __restrict__ res,
         float* __restrict__ out, int M, int N, int K, int do_gelu, int round_out) {
    extern __shared__ char smch[];
    uint32_t smemu = (uint32_t)__cvta_generic_to_shared(smch);

    int tid  = threadIdx.x;
    int lane = tid & 31;
    int wid  = tid >> 5;
    int wm   = (wid >> 2) * 64;
    int wn   = (wid & 3) * 32;
    int m0 = blockIdx.y * GBM, n0 = blockIdx.x * GBN;

    int lq = lane >> 2;
    int lr = lane & 3;

    int lrow = (lane & 7) + ((lane >> 3) & 1) * 8;
    int lcol = (lane >> 4) * 4;

    int arow = tid >> 1, ac0 = (tid & 1);
    int brow = tid >> 5, bc = tid & 31;

    const float* Asrc0 = A + (size_t)(m0 + arow) * K + ac0 * 4;
    const float* Asrc1 = A + (size_t)(m0 + arow) * K + (ac0 + 2) * 4;
    const float* Bsrc0 = W + (size_t)brow * N + n0 + bc * 4;
    const float* Bsrc1 = W + (size_t)(brow + 8) * N + n0 + bc * 4;

    uint32_t adst0 = smemu + arow * (APITCH * 4) + ac0 * 16;
    uint32_t adst1 = adst0 + 32;
    uint32_t bbase = smemu + NSTAGES * ASTAGE;
    uint32_t bdst0 = bbase + brow * (BPITCH * 4) + bc * 16;
    uint32_t bdst1 = bdst0 + 8 * (BPITCH * 4);

    float acc[4][4][4];
    #pragma unroll
    for (int i = 0; i < 4; i++)
        #pragma unroll
        for (int j = 0; j < 4; j++)
            #pragma unroll
            for (int r = 0; r < 4; r++) acc[i][j][r] = 0.f;

    const int NC = K / GBK;

    #pragma unroll
    for (int s = 0; s < NSTAGES - 1; s++) {
        size_t ko = (size_t)s * GBK;
        CP_ASYNC16(adst0 + s * ASTAGE, Asrc0 + ko);
        CP_ASYNC16(adst1 + s * ASTAGE, Asrc1 + ko);
        CP_ASYNC16(bdst0 + s * BSTAGE, Bsrc0 + ko * N);
        CP_ASYNC16(bdst1 + s * BSTAGE, Bsrc1 + ko * N);
        CP_COMMIT();
    }

    for (int c = 0; c < NC; c++) {
        CP_WAIT2();
        __syncthreads();

        int st = c & (NSTAGES - 1);
        uint32_t aST = smemu + st * ASTAGE;
        const uint32_t* BsP = (const uint32_t*)(smch + NSTAGES * ASTAGE + st * BSTAGE);

        #pragma unroll
        for (int ks = 0; ks < 2; ks++) {
            int k8 = ks * 8;
            uint32_t a[4][4], b[4][2];
            #pragma unroll
            for (int mt = 0; mt < 4; mt++) {
                uint32_t addr = aST + (((wm + mt * 16 + lrow) * APITCH) + k8 + lcol) * 4;
                ldmatrix_x4(a[mt], addr);
            }
            #pragma unroll
            for (int nt = 0; nt < 4; nt++) {
                int cn = wn + nt * 8 + lq;
                b[nt][0] = BsP[(k8 + lr) * BPITCH + cn];
                b[nt][1] = BsP[(k8 + 4 + lr) * BPITCH + cn];
            }
            #pragma unroll
            for (int mt = 0; mt < 4; mt++)
                #pragma unroll
                for (int nt = 0; nt < 4; nt++)
                    mma_tf32(acc[mt][nt], a[mt], b[nt], acc[mt][nt]);
        }

        int nc = c + NSTAGES - 1;
        if (nc < NC) {
            int s = nc & (NSTAGES - 1);
            size_t ko = (size_t)nc * GBK;
            CP_ASYNC16(adst0 + s * ASTAGE, Asrc0 + ko);
            CP_ASYNC16(adst1 + s * ASTAGE, Asrc1 + ko);
            CP_ASYNC16(bdst0 + s * BSTAGE, Bsrc0 + ko * N);
            CP_ASYNC16(bdst1 + s * BSTAGE, Bsrc1 + ko * N);
        }
        CP_COMMIT();
    }

    #pragma unroll
    for (int mt = 0; mt < 4; mt++) {
        int row0 = m0 + wm + mt * 16 + lq;
        #pragma unroll
        for (int nt = 0; nt < 4; nt++) {
            int col = n0 + wn + nt * 8 + lr * 2;
            #pragma unroll
            for (int half = 0; half < 2; half++) {
                int row = row0 + half * 8;
                float v0 = acc[mt][nt][half * 2 + 0];
                float v1 = acc[mt][nt][half * 2 + 1];
                if (bias) {
                    v0 += __ldg(bias + col);
                    v1 += __ldg(bias + col + 1);
                }
                if (do_gelu) {
                    v0 = 0.5f * v0 * (1.0f + erff(v0 * 0.70710678118654752f));
                    v1 = 0.5f * v1 * (1.0f + erff(v1 * 0.70710678118654752f));
                }
                if (res) {
                    const float2 rr = *(const float2*)(res + (size_t)row * N + col);
                    v0 += rr.x; v1 += rr.y;
                }
                if (round_out) { v0 = f2tf32f(v0); v1 = f2tf32f(v1); }
                float2 o2; o2.x = v0; o2.y = v1;
                *(float2*)(out + (size_t)row * N + col) = o2;
            }
        }
    }
}

// ============================== tensor-core flash attention (tf32) ==============================
// Block: 128 threads (4 warps). Each warp owns 16 q-rows of a 64-row q-tile.
// K in SMEM as [d][s] with dual-XOR swizzle (conflict-free b-frag reads).
// V in SMEM as [s][d] pitch 72 (conflict-free b-frag reads).
// P per-warp SMEM [16][72] (no block barrier needed for P).
#define VPITCH 72
#define PPITCH 72
#define ATTN_K_WORDS  (64 * 64)            // 4096
#define ATTN_V_WORDS  (64 * VPITCH)        // 4608
#define ATTN_P_WORDS  (4 * 16 * PPITCH)    // 4608
#define ATTN_SMEM ((ATTN_K_WORDS + ATTN_V_WORDS + ATTN_P_WORDS) * 4)   // 53248 B

__global__ void __launch_bounds__(128)
attn_kernel(const float* __restrict__ q, const float* __restrict__ k,
            const float* __restrict__ v, float* __restrict__ o) {
    extern __shared__ float sm[];
    float* Ks = sm;                                   // swizzled [d][s]
    float* Vs = sm + ATTN_K_WORDS;                    // [s][d] pitch 72
    float* Ps = sm + ATTN_K_WORDS + ATTN_V_WORDS;     // per-warp [16][72]

    int tid  = threadIdx.x;
    int lane = tid & 31;
    int wid  = tid >> 5;
    int lq = lane >> 2;      // 0..7
    int lr = lane & 3;       // 0..3

    int qt0 = blockIdx.x * 64;
    int h = blockIdx.y, b = blockIdx.z;
    size_t base = ((size_t)b * TT) * CC + (size_t)h * DD;

    // ---- Q a-fragments in registers (rows wid*16 + lq / +8), pre-scaled ----
    uint32_t qa[8][4];
    {
        const float* q0 = q + base + (size_t)(qt0 + wid * 16 + lq) * CC;
        const float* q1 = q0 + 8 * CC;
        #pragma unroll
        for (int ks = 0; ks < 8; ks++) {
            qa[ks][0] = f2tf32(q0[ks * 8 + lr] * 0.125f);
            qa[ks][1] = f2tf32(q1[ks * 8 + lr] * 0.125f);
            qa[ks][2] = f2tf32(q0[ks * 8 + 4 + lr] * 0.125f);
            qa[ks][3] = f2tf32(q1[ks * 8 + 4 + lr] * 0.125f);
        }
    }

    float m0r = -1e30f, m1r = -1e30f, l0r = 0.f, l1r = 0.f;
    float accO[8][4];
    #pragma unroll
    for (int nt = 0; nt < 8; nt++)
        #pragma unroll
        for (int j = 0; j < 4; j++) accO[nt][j] = 0.f;

    float* Pw = Ps + wid * 16 * PPITCH;

    for (int s0 = 0; s0 < TT; s0 += 64) {
        __syncthreads();
        // ---- fill K (swizzled transpose) and V ----
        #pragma unroll
        for (int i = 0; i < 8; i++) {
            int idx4 = tid + i * 128;          // 0..1023
            int r = idx4 >> 4, d4 = idx4 & 15;
            float4 kv = *(const float4*)(k + base + (size_t)(s0 + r) * CC + d4 * 4);
            int sw = r ^ (d4 & 7);
            Ks[(d4 * 4 + 0) * 64 + (sw ^ 0 )] = __uint_as_float(f2tf32(kv.x));
            Ks[(d4 * 4 + 1) * 64 + (sw ^ 8 )] = __uint_as_float(f2tf32(kv.y));
            Ks[(d4 * 4 + 2) * 64 + (sw ^ 16)] = __uint_as_float(f2tf32(kv.z));
            Ks[(d4 * 4 + 3) * 64 + (sw ^ 24)] = __uint_as_float(f2tf32(kv.w));

            float4 vv = *(const float4*)(v + base + (size_t)(s0 + r) * CC + d4 * 4);
            float* vp = &Vs[r * VPITCH + d4 * 4];
            vp[0] = f2tf32f(vv.x); vp[1] = f2tf32f(vv.y);
            vp[2] = f2tf32f(vv.z); vp[3] = f2tf32f(vv.w);
        }
        __syncthreads();

        // ---- S = Q @ K^T (64 MMAs per warp) ----
        float sacc[8][4];
        #pragma unroll
        for (int nt = 0; nt < 8; nt++)
            #pragma unroll
            for (int j = 0; j < 4; j++) sacc[nt][j] = 0.f;

        #pragma unroll
        for (int ks = 0; ks < 8; ks++) {
            int d0 = ks * 8 + lr;        // b0 k-row
            int d1 = d0 + 4;             // b1 k-row
            int sw0 = (lr << 3) ^ ((2 * ks) & 7);
            int sw1 = (lr << 3) ^ ((2 * ks + 1) & 7);
            #pragma unroll
            for (int nt = 0; nt < 8; nt++) {
                uint32_t bfr[2];
                bfr[0] = __float_as_uint(Ks[d0 * 64 + ((nt * 8 + lq) ^ sw0)]);
                bfr[1] = __float_as_uint(Ks[d1 * 64 + ((nt * 8 + lq) ^ sw1)]);
                mma_tf32(sacc[nt], qa[ks], bfr, sacc[nt]);
            }
        }

        // ---- online softmax (quad-local) ----
        float tm0 = -1e30f, tm1 = -1e30f;
        #pragma unroll
        for (int nt = 0; nt < 8; nt++) {
            tm0 = fmaxf(tm0, fmaxf(sacc[nt][0], sacc[nt][1]));
            tm1 = fmaxf(tm1, fmaxf(sacc[nt][2], sacc[nt][3]));
        }
        tm0 = fmaxf(tm0, __shfl_xor_sync(0xffffffffu, tm0, 1));
        tm0 = fmaxf(tm0, __shfl_xor_sync(0xffffffffu, tm0, 2));
        tm1 = fmaxf(tm1, __shfl_xor_sync(0xffffffffu, tm1, 1));
        tm1 = fmaxf(tm1, __shfl_xor_sync(0xffffffffu, tm1, 2));

        float mn0 = fmaxf(m0r, tm0);
        float mn1 = fmaxf(m1r, tm1);
        float cr0 = __expf(m0r - mn0);
        float cr1 = __expf(m1r - mn1);
        m0r = mn0; m1r = mn1;

        float rs0 = 0.f, rs1 = 0.f;
        #pragma unroll
        for (int nt = 0; nt < 8; nt++) {
            sacc[nt][0] = __expf(sacc[nt][0] - mn0);
            sacc[nt][1] = __expf(sacc[nt][1] - mn0);
            sacc[nt][2] = __expf(sacc[nt][2] - mn1);
            sacc[nt][3] = __expf(sacc[nt][3] - mn1);
            rs0 += sacc[nt][0] + sacc[nt][1];
            rs1 += sacc[nt][2] + sacc[nt][3];
        }
        rs0 += __shfl_xor_sync(0xffffffffu, rs0, 1);
        rs0 += __shfl_xor_sync(0xffffffffu, rs0, 2);
        rs1 += __shfl_xor_sync(0xffffffffu, rs1, 1);
        rs1 += __shfl_xor_sync(0xffffffffu, rs1, 2);
        l0r = l0r * cr0 + rs0;
        l1r = l1r * cr1 + rs1;

        #pragma unroll
        for (int nt = 0; nt < 8; nt++) {
            accO[nt][0] *= cr0; accO[nt][1] *= cr0;
            accO[nt][2] *= cr1; accO[nt][3] *= cr1;
        }

        // ---- stage P (tf32-rounded) into per-warp SMEM ----
        __syncwarp();
        #pragma unroll
        for (int nt = 0; nt < 8; nt++) {
            float2 p01; p01.x = f2tf32f(sacc[nt][0]); p01.y = f2tf32f(sacc[nt][1]);
            float2 p23; p23.x = f2tf32f(sacc[nt][2]); p23.y = f2tf32f(sacc[nt][3]);
            *(float2*)&Pw[lq * PPITCH + nt * 8 + 2 * lr]       = p01;
            *(float2*)&Pw[(lq + 8) * PPITCH + nt * 8 + 2 * lr] = p23;
        }
        __syncwarp();

        // ---- accO += P @ V (64 MMAs per warp) ----
        #pragma unroll
        for (int ks = 0; ks < 8; ks++) {
            uint32_t pa[4];
            pa[0] = __float_as_uint(Pw[lq * PPITCH + ks * 8 + lr]);
            pa[1] = __float_as_uint(Pw[(lq + 8) * PPITCH + ks * 8 + lr]);
            pa[2] = __float_as_uint(Pw[lq * PPITCH + ks * 8 + 4 + lr]);
            pa[3] = __float_as_uint(Pw[(lq + 8) * PPITCH + ks * 8 + 4 + lr]);
            #pragma unroll
            for (int nt = 0; nt < 8; nt++) {
                uint32_t bfr[2];
                bfr[0] = __float_as_uint(Vs[(ks * 8 + lr) * VPITCH + nt * 8 + lq]);
                bfr[1] = __float_as_uint(Vs[(ks * 8 + 4 + lr) * VPITCH + nt * 8 + lq]);
                mma_tf32(accO[nt], pa, bfr, accO[nt]);
            }
        }
    }

    // ---- output (rounded tf32: feeds next GEMM) ----
    float inv0 = 1.0f / l0r, inv1 = 1.0f / l1r;
    int row0 = qt0 + wid * 16 + lq;
    #pragma unroll
    for (int nt = 0; nt < 8; nt++) {
        float2 o0, o1;
        o0.x = f2tf32f(accO[nt][0] * inv0); o0.y = f2tf32f(accO[nt][1] * inv0);
        o1.x = f2tf32f(accO[nt][2] * inv1); o1.y = f2tf32f(accO[nt][3] * inv1);
        *(float2*)(o + base + (size_t)row0 * CC + nt * 8 + 2 * lr)       = o0;
        *(float2*)(o + base + (size_t)(row0 + 8) * CC + nt * 8 + 2 * lr) = o1;
    }
}

// ============================== launcher ==============================
extern "C" void kernel_launch(void* const* d_in, const int* in_sizes, int n_in,
                              void* d_out, int out_size) {
    (void)in_sizes; (void)n_in; (void)out_size;

    const int*   src     = (const int*)  d_in[0];
    const float* src_emb = (const float*)d_in[1];
    const float* pos_emb = (const float*)d_in[2];
    const float* ln1_w   = (const float*)d_in[3];
    const float* ln1_b   = (const float*)d_in[4];
    const float* wq      = (const float*)d_in[5];
    const float* bq      = (const float*)d_in[6];
    const float* wk      = (const float*)d_in[7];
    const float* bk      = (const float*)d_in[8];
    const float* wv      = (const float*)d_in[9];
    const float* bv      = (const float*)d_in[10];
    const float* wo      = (const float*)d_in[11];
    const float* bo      = (const float*)d_in[12];
    const float* ln2_w   = (const float*)d_in[13];
    const float* ln2_b   = (const float*)d_in[14];
    const float* w1      = (const float*)d_in[15];
    const float* b1      = (const float*)d_in[16];
    const float* w2      = (const float*)d_in[17];
    const float* b2      = (const float*)d_in[18];
    const float* lnf_w   = (const float*)d_in[19];
    const float* lnf_b   = (const float*)d_in[20];
    const float* head_w  = (const float*)d_in[21];

    float *xb, *hb, *qb, *kb, *vb, *ob, *fb, *wT;
    cudaGetSymbolAddress((void**)&xb, g_x);
    cudaGetSymbolAddress((void**)&hb, g_h);
    cudaGetSymbolAddress((void**)&qb, g_q);
    cudaGetSymbolAddress((void**)&kb, g_k);
    cudaGetSymbolAddress((void**)&vb, g_v);
    cudaGetSymbolAddress((void**)&ob, g_o);
    cudaGetSymbolAddress((void**)&fb, g_ff);
    cudaGetSymbolAddress((void**)&wT, g_wT);

    cudaFuncSetAttribute(attn_kernel, cudaFuncAttributeMaxDynamicSharedMemorySize, ATTN_SMEM);
    cudaFuncSetAttribute(mma_gemm, cudaFuncAttributeMaxDynamicSharedMemorySize, GEMM_SMEM);

    embed_kernel<<<MT, 256>>>(src, src_emb, pos_emb, xb);

    dim3 gC(CC / GBN, MT / GBM);    // (8, 32)
    dim3 gF(FFD / GBN, MT / GBM);   // (32, 32)
    dim3 gH(VV / GBN, MT / GBM);    // (250, 32)
    dim3 gA(TT / 64, HH, BSZ);

    const int RB_CC = (CC * CC) / 1024;
    const int RB_FF = (CC * FFD) / 1024;
    const int RB_HD = (VV * CC) / 1024;

    for (int l = 0; l < LL; l++) {
        size_t wOff  = (size_t)l * CC * CC;
        size_t w1Off = (size_t)l * CC * FFD;
        size_t w2Off = (size_t)l * FFD * CC;

        ln_kernel<<<MT, 256>>>(xb, ln1_w + l * CC, ln1_b + l * CC, hb);

        round_tf32_kernel<<<RB_CC, 256>>>(wq + wOff, wT);
        mma_gemm<<<gC, 256, GEMM_SMEM>>>(hb, wT, bq + l * CC, nullptr, qb, MT, CC, CC, 0, 0);
        round_tf32_kernel<<<RB_CC, 256>>>(wk + wOff, wT);
        mma_gemm<<<gC, 256, GEMM_SMEM>>>(hb, wT, bk + l * CC, nullptr, kb, MT, CC, CC, 0, 0);
        round_tf32_kernel<<<RB_CC, 256>>>(wv + wOff, wT);
        mma_gemm<<<gC, 256, GEMM_SMEM>>>(hb, wT, bv + l * CC, nullptr, vb, MT, CC, CC, 0, 0);

        attn_kernel<<<gA, 128, ATTN_SMEM>>>(qb, kb, vb, ob);

        round_tf32_kernel<<<RB_CC, 256>>>(wo + wOff, wT);
        mma_gemm<<<gC, 256, GEMM_SMEM>>>(ob, wT, bo + l * CC, xb, xb, MT, CC, CC, 0, 0);

        ln_kernel<<<MT, 256>>>(xb, ln2_w + l * CC, ln2_b + l * CC, hb);

        round_tf32_kernel<<<RB_FF, 256>>>(w1 + w1Off, wT);
        mma_gemm<<<gF, 256, GEMM_SMEM>>>(hb, wT, b1 + l * FFD, nullptr, fb, MT, FFD, CC, 1, 1);
        round_tf32_kernel<<<RB_FF, 256>>>(w2 + w2Off, wT);
        mma_gemm<<<gC, 256, GEMM_SMEM>>>(fb, wT, b2 + l * CC, xb, xb, MT, CC, FFD, 0, 0);
    }

    ln_kernel<<<MT, 256>>>(xb, lnf_w, lnf_b, hb);
    round_tf32_kernel<<<RB_HD, 256>>>(head_w, wT);
    mma_gemm<<<gH, 256, GEMM_SMEM>>>(hb, wT, nullptr, nullptr, (float*)d_out, MT, VV, CC, 0, 0);
}